// round 10
// baseline (speedup 1.0000x reference)
#include <cuda_runtime.h>
#include <cuda_bf16.h>
#include <cuda_fp16.h>

#define BATCH 2
#define SEQ   2048
#define DIM   1024
#define NH    16
#define HD    64
#define MROWS (BATCH*SEQ)   // 4096
#define QKVN  (3*DIM)       // 3072
#define LOG2E 1.4426950408889634f

// ---------------- scratch (__device__ globals; no runtime allocs) ----------
__device__ __half g_Qh[(size_t)BATCH*NH*SEQ*HD];     // fp16, pre-scaled 0.125*log2e
__device__ __half g_Kh[(size_t)BATCH*NH*SEQ*HD];
__device__ __half g_Vh[(size_t)BATCH*NH*SEQ*HD];
__device__ __half g_X16[(size_t)MROWS*DIM];          // x in fp16
__device__ __half g_W1hi[(size_t)QKVN*DIM];          // Wqkv^T hi/lo fp16
__device__ __half g_W1lo[(size_t)QKVN*DIM];
__device__ __half g_W2hi[(size_t)DIM*DIM];           // Wout^T hi/lo fp16
__device__ __half g_W2lo[(size_t)DIM*DIM];
__device__ __half g_AOh[(size_t)MROWS*DIM];          // attention out fp16
__device__ __half g_MB[(size_t)BATCH*SEQ*SEQ];       // (mask + bias)*log2e (fp16)

// ---------------- helpers ---------------------------------------------------
__device__ __forceinline__ unsigned smem_u32(const void* p) {
    unsigned a;
    asm("{ .reg .u64 t; cvta.to.shared.u64 t, %1; cvt.u32.u64 %0, t; }"
        : "=r"(a) : "l"(p));
    return a;
}
__device__ __forceinline__ void ldsm4(unsigned& r0, unsigned& r1,
                                      unsigned& r2, unsigned& r3, unsigned a) {
    asm volatile("ldmatrix.sync.aligned.m8n8.x4.shared.b16 {%0,%1,%2,%3}, [%4];"
                 : "=r"(r0), "=r"(r1), "=r"(r2), "=r"(r3) : "r"(a));
}
__device__ __forceinline__ void ldsm4t(unsigned& r0, unsigned& r1,
                                       unsigned& r2, unsigned& r3, unsigned a) {
    asm volatile("ldmatrix.sync.aligned.m8n8.x4.trans.shared.b16 {%0,%1,%2,%3}, [%4];"
                 : "=r"(r0), "=r"(r1), "=r"(r2), "=r"(r3) : "r"(a));
}
__device__ __forceinline__ void mma_f16(float* c, const unsigned* a,
                                        unsigned b0, unsigned b1) {
    asm volatile(
        "mma.sync.aligned.m16n8k16.row.col.f32.f16.f16.f32 "
        "{%0,%1,%2,%3}, {%4,%5,%6,%7}, {%8,%9}, {%0,%1,%2,%3};"
        : "+f"(c[0]), "+f"(c[1]), "+f"(c[2]), "+f"(c[3])
        : "r"(a[0]), "r"(a[1]), "r"(a[2]), "r"(a[3]), "r"(b0), "r"(b1));
}
__device__ __forceinline__ void cp16(unsigned dst, const void* src) {
    asm volatile("cp.async.cg.shared.global [%0], [%1], 16;"
                 :: "r"(dst), "l"(src) : "memory");
}
__device__ __forceinline__ void cp_commit() {
    asm volatile("cp.async.commit_group;" ::: "memory");
}
__device__ __forceinline__ unsigned packh2(float a, float b) {
    unsigned r;
    asm("cvt.rn.f16x2.f32 %0, %1, %2;" : "=r"(r) : "f"(b), "f"(a));
    return r;
}
// MUFU 2^t
__device__ __forceinline__ float ex2f(float t) {
    float r;
    asm("ex2.approx.f32 %0, %1;" : "=f"(r) : "f"(t));
    return r;
}
// swizzled offset in a [rows][32 f16] tile (64B rows)
__device__ __forceinline__ unsigned swz64(int row, unsigned colb) {
    return (unsigned)(row * 64) + (colb ^ (((unsigned)(row >> 1) & 3u) << 4));
}

#define GEMM_STAGE 24576            // A 8KB | Bhi 8KB | Blo 8KB
#define GEMM_SMEM  (3*GEMM_STAGE)   // 72 KB

// ---------------------------------------------------------------------------
// conversions
// ---------------------------------------------------------------------------
__global__ __launch_bounds__(256) void conv_x16_kernel(
    const float* __restrict__ src, __half* __restrict__ dst, int n4)
{
    int i = blockIdx.x * 256 + threadIdx.x;
    if (i >= n4) return;
    float4 v = *((const float4*)src + i);
    uint2 o;
    o.x = packh2(v.x, v.y);
    o.y = packh2(v.z, v.w);
    ((uint2*)dst)[i] = o;
}

// transpose + fp16 split: W[K][N] -> T{hi,lo}[N][K]
__global__ void conv_transpose_kernel(
    const float* __restrict__ W, __half* __restrict__ Thi,
    __half* __restrict__ Tlo, int K, int N)
{
    __shared__ float t[32][33];
    const int k0 = blockIdx.x * 32, n0 = blockIdx.y * 32;
    const int tx = threadIdx.x, ty = threadIdx.y;
    for (int i = ty; i < 32; i += 8)
        t[i][tx] = W[(size_t)(k0 + i) * N + n0 + tx];
    __syncthreads();
    for (int i = ty; i < 32; i += 8) {
        float v = t[tx][i];
        __half h = __float2half(v);
        Thi[(size_t)(n0 + i) * K + k0 + tx] = h;
        Tlo[(size_t)(n0 + i) * K + k0 + tx] = __float2half(v - __half2float(h));
    }
}

// combined (mask+bias)*log2e in fp16
__global__ __launch_bounds__(256) void mb_kernel(
    const float* __restrict__ mask, const float* __restrict__ bias, int n8)
{
    int i = blockIdx.x * 256 + threadIdx.x;
    if (i >= n8) return;
    const int per_b = SEQ * SEQ / 8;
    int r = i % per_b;
    float4 m0 = ((const float4*)mask)[r*2+0];
    float4 m1 = ((const float4*)mask)[r*2+1];
    float4 b0 = ((const float4*)bias)[i*2+0];
    float4 b1 = ((const float4*)bias)[i*2+1];
    __half2 o[4];
    o[0] = __floats2half2_rn((m0.x + b0.x) * LOG2E, (m0.y + b0.y) * LOG2E);
    o[1] = __floats2half2_rn((m0.z + b0.z) * LOG2E, (m0.w + b0.w) * LOG2E);
    o[2] = __floats2half2_rn((m1.x + b1.x) * LOG2E, (m1.y + b1.y) * LOG2E);
    o[3] = __floats2half2_rn((m1.z + b1.z) * LOG2E, (m1.w + b1.w) * LOG2E);
    ((uint4*)g_MB)[i] = *(uint4*)o;
}

// ---------------------------------------------------------------------------
// HMMA GEMM: A fp16 single, B fp16 hi+lo split (2 MMAs). BK=32, 3-stage
// single-sync cp.async pipeline, 2 CTAs/SM.
// mode 0: out fp32 + bias. mode 1: emit fp16 Q (scaled 0.125*log2e) / K / V.
// ---------------------------------------------------------------------------
__global__ __launch_bounds__(256, 2) void mma_gemm_kernel(
    const __half* __restrict__ A,
    const __half* __restrict__ Bhi, const __half* __restrict__ Blo,
    const float* __restrict__ bias, float* __restrict__ out, int mode)
{
    extern __shared__ char smraw[];
    const unsigned sbase = smem_u32(smraw);
    const int tid  = threadIdx.x;
    const int wid  = tid >> 5;
    const int lane = tid & 31;
    const int warp_m = wid & 3;
    const int warp_n = wid >> 2;
    const int row_a = blockIdx.y * 128;
    const int col0  = blockIdx.x * 128;

    float acc[2][8][4];
#pragma unroll
    for (int i = 0; i < 2; i++)
#pragma unroll
        for (int j = 0; j < 8; j++)
#pragma unroll
            for (int c = 0; c < 4; c++) acc[i][j][c] = 0.f;

    auto issue = [&](int t) {
        const int k0 = t * 32;
        const unsigned stage = (unsigned)((t % 3) * GEMM_STAGE);
#pragma unroll
        for (int p = 0; p < 3; p++) {
            const __half* src = (p == 0) ? A : (p == 1) ? Bhi : Blo;
            const int rb = (p == 0) ? row_a : col0;
            const unsigned pb = stage + (unsigned)p * 8192u;
#pragma unroll
            for (int i = 0; i < 2; i++) {
                const int e = tid + i * 256;
                const int r = e >> 2, c16 = e & 3;
                cp16(sbase + pb + swz64(r, (unsigned)(c16 * 16)),
                     src + (size_t)(rb + r) * DIM + k0 + c16 * 8);
            }
        }
        cp_commit();
    };

    issue(0); issue(1);

    const int amat = lane >> 3;
    const int arow_l = (lane & 7) + ((amat & 1) << 3);
    const unsigned acolx = (unsigned)((amat >> 1) << 4);
    const int brow_l = (lane & 7) + ((amat >> 1) << 3);
    const unsigned bcolx = (unsigned)((amat & 1) << 4);

    for (int t = 0; t < 32; t++) {
        if (t < 31) asm volatile("cp.async.wait_group 1;" ::: "memory");
        else        asm volatile("cp.async.wait_group 0;" ::: "memory");
        __syncthreads();
        if (t + 2 < 32) issue(t + 2);

        const unsigned stage = sbase + (unsigned)((t % 3) * GEMM_STAGE);
#pragma unroll
        for (int ks = 0; ks < 2; ks++) {
            const unsigned kb = (unsigned)(ks * 32);
            unsigned bh[4][4], bl[4][4];
#pragma unroll
            for (int np = 0; np < 4; np++) {
                const int r = warp_n * 64 + np * 16 + brow_l;
                const unsigned ro = swz64(r, kb + bcolx);
                ldsm4(bh[np][0], bh[np][1], bh[np][2], bh[np][3], stage + 8192 + ro);
                ldsm4(bl[np][0], bl[np][1], bl[np][2], bl[np][3], stage + 16384 + ro);
            }
#pragma unroll
            for (int mf = 0; mf < 2; mf++) {
                const int r = warp_m * 32 + mf * 16 + arow_l;
                const unsigned ro = swz64(r, kb + acolx);
                unsigned af[4];
                ldsm4(af[0], af[1], af[2], af[3], stage + ro);
#pragma unroll
                for (int nn = 0; nn < 8; nn++) {
                    const int np = nn >> 1, hf = (nn & 1) * 2;
                    mma_f16(acc[mf][nn], af, bh[np][hf], bh[np][hf + 1]);
                    mma_f16(acc[mf][nn], af, bl[np][hf], bl[np][hf + 1]);
                }
            }
        }
    }

#pragma unroll
    for (int mf = 0; mf < 2; mf++) {
#pragma unroll
        for (int nn = 0; nn < 8; nn++) {
            const int gc = col0 + warp_n * 64 + nn * 8 + (lane & 3) * 2;
            const int r0 = row_a + warp_m * 32 + mf * 16 + (lane >> 2);
            const float bx = bias[gc], by = bias[gc + 1];
            float2 v0, v1;
            v0.x = acc[mf][nn][0] + bx; v0.y = acc[mf][nn][1] + by;
            v1.x = acc[mf][nn][2] + bx; v1.y = acc[mf][nn][3] + by;
            if (mode == 0) {
                *(float2*)(out + (size_t)r0 * DIM + gc)       = v0;
                *(float2*)(out + (size_t)(r0 + 8) * DIM + gc) = v1;
            } else {
                const int sel = gc >> 10;
                const int w   = gc & 1023;
                const int h   = w >> 6;
                const int d0  = w & 63;
                __half* dst;
                float sc;
                if (sel == 0)      { dst = g_Qh; sc = 0.125f * LOG2E; }
                else if (sel == 1) { dst = g_Kh; sc = 1.f; }
                else               { dst = g_Vh; sc = 1.f; }
                const int b0 = r0 >> 11, s0 = r0 & 2047;
                const int r1 = r0 + 8;
                const int b1 = r1 >> 11, s1 = r1 & 2047;
                const size_t i0 = (((size_t)b0 * NH + h) * SEQ + s0) * HD + d0;
                const size_t i1 = (((size_t)b1 * NH + h) * SEQ + s1) * HD + d0;
                *(unsigned*)(dst + i0) = packh2(v0.x * sc, v0.y * sc);
                *(unsigned*)(dst + i1) = packh2(v1.x * sc, v1.y * sc);
            }
        }
    }
}

// ---------------------------------------------------------------------------
// fp16 flash attention (log2-domain, MUFU exp2). 128 q x 128 k tiles,
// 8 warps, 2 CTAs/SM, THREE-stage single-sync pipeline; 16 iterations.
// (2-stage + issue(t+2) is a race: stage(t+2)==stage(t).)
// ---------------------------------------------------------------------------
#define ATTN_STAGE 32768                     // K 16KB | V 16KB
#define ATTN_SMEM  (16384 + 3*ATTN_STAGE)    // 112 KB -> 2 CTAs = 224 KB/SM

__global__ __launch_bounds__(256, 2) void attn_mma_kernel()
{
    extern __shared__ char smraw[];
    const unsigned sbase = smem_u32(smraw);
    const int tid = threadIdx.x, wid = tid >> 5, lane = tid & 31;
    const int bh = blockIdx.y, b = bh >> 4, h = bh & 15;
    const int q0 = blockIdx.x * 128;

    const __half* Qg = g_Qh + (size_t)bh * SEQ * HD;
    const __half* Kg = g_Kh + (size_t)bh * SEQ * HD;
    const __half* Vg = g_Vh + (size_t)bh * SEQ * HD;

    // Q tile -> smem (128B rows, 128B swizzle), own commit group
#pragma unroll
    for (int i = 0; i < 4; i++) {
        const int e = tid + i * 256;
        const int r = e >> 3, c4 = e & 7;
        unsigned off = (unsigned)(r * 128 + c4 * 16);
        off ^= (off >> 3) & 0x70;
        cp16(sbase + off, Qg + (size_t)(q0 + r) * HD + c4 * 8);
    }
    cp_commit();

    // stage: 128 keys of K then 128 keys of V
    auto issue = [&](int t) {
        const int k0 = t * 128;
        const unsigned stg = 16384u + (unsigned)((t % 3) * ATTN_STAGE);
#pragma unroll
        for (int p = 0; p < 2; p++) {
            const __half* src = p ? Vg : Kg;
#pragma unroll
            for (int i = 0; i < 4; i++) {
                const int e = tid + i * 256;       // 0..1023
                const int r = e >> 3, c4 = e & 7;
                unsigned off = (unsigned)(r * 128 + c4 * 16);
                off ^= (off >> 3) & 0x70;
                cp16(sbase + stg + (unsigned)p * 16384u + off,
                     src + (size_t)(k0 + r) * HD + c4 * 8);
            }
        }
        cp_commit();
    };
    issue(0); issue(1);

    const int amat = lane >> 3;
    const int arow = wid * 16 + (lane & 7) + ((amat & 1) << 3);
    const unsigned acolx = (unsigned)((amat >> 1) << 4);
    const int krow_b = (lane & 7) + ((amat >> 1) << 3);
    const unsigned kcolx = (unsigned)((amat & 1) << 4);
    const int vrow_b = (lane & 7) + ((amat & 1) << 3);
    const unsigned vcolb = (unsigned)((lane >> 4) << 4);

    const __half* mbp = g_MB + ((size_t)b * SEQ + q0 + wid * 16 + (lane >> 2)) * SEQ
                        + (lane & 3) * 2;

    float o[8][4];
#pragma unroll
    for (int nn = 0; nn < 8; nn++)
#pragma unroll
        for (int c = 0; c < 4; c++) o[nn][c] = 0.f;
    float sM0 = -1e30f, sM1 = -1e30f, sAcc0 = 0.f, sAcc1 = 0.f;

    for (int t = 0; t < 16; t++) {
        if (t < 15) asm volatile("cp.async.wait_group 1;" ::: "memory");
        else        asm volatile("cp.async.wait_group 0;" ::: "memory");
        __syncthreads();
        if (t + 2 < 16) issue(t + 2);

        const unsigned stg = sbase + 16384u + (unsigned)((t % 3) * ATTN_STAGE);

        // ---- S = Q.K^T over 128 keys (fp16, log2-domain) ----
        float s[16][4];
#pragma unroll
        for (int nn = 0; nn < 16; nn++)
#pragma unroll
            for (int c = 0; c < 4; c++) s[nn][c] = 0.f;
#pragma unroll
        for (int ks = 0; ks < 4; ks++) {
            unsigned qoff = (unsigned)(arow * 128)
                          + (((unsigned)(ks * 32) + acolx) ^ (((unsigned)(arow & 7)) << 4));
            unsigned qf[4];
            ldsm4(qf[0], qf[1], qf[2], qf[3], sbase + qoff);
#pragma unroll
            for (int np = 0; np < 8; np++) {
                const int kr = np * 16 + krow_b;
                unsigned off = (unsigned)(kr * 128)
                             + (((unsigned)(ks * 32) + kcolx) ^ (((unsigned)(kr & 7)) << 4));
                unsigned kf[4];
                ldsm4(kf[0], kf[1], kf[2], kf[3], stg + off);
                mma_f16(s[2*np],   qf, kf[0], kf[1]);
                mma_f16(s[2*np+1], qf, kf[2], kf[3]);
            }
        }

        // ---- + (mask+bias)*log2e (fp16) ----
        const __half* mrow = mbp + t * 128;
#pragma unroll
        for (int nn = 0; nn < 16; nn++) {
            float2 f0 = __half22float2(*(const __half2*)(mrow + nn * 8));
            float2 f1 = __half22float2(*(const __half2*)(mrow + 8 * SEQ + nn * 8));
            s[nn][0] += f0.x; s[nn][1] += f0.y;
            s[nn][2] += f1.x; s[nn][3] += f1.y;
        }

        // ---- online softmax (log2-domain, MUFU exp2) ----
        float mx0 = -1e30f, mx1 = -1e30f;
#pragma unroll
        for (int nn = 0; nn < 16; nn++) {
            mx0 = fmaxf(mx0, fmaxf(s[nn][0], s[nn][1]));
            mx1 = fmaxf(mx1, fmaxf(s[nn][2], s[nn][3]));
        }
        mx0 = fmaxf(mx0, __shfl_xor_sync(0xffffffffu, mx0, 1));
        mx0 = fmaxf(mx0, __shfl_xor_sync(0xffffffffu, mx0, 2));
        mx1 = fmaxf(mx1, __shfl_xor_sync(0xffffffffu, mx1, 1));
        mx1 = fmaxf(mx1, __shfl_xor_sync(0xffffffffu, mx1, 2));
        const float old0 = sM0, old1 = sM1;
        const float mn0 = fmaxf(sM0, mx0), mn1 = fmaxf(sM1, mx1);
        sM0 = mn0; sM1 = mn1;

        float ls0 = 0.f, ls1 = 0.f;
#pragma unroll
        for (int nn = 0; nn < 16; nn++) {
            s[nn][0] = ex2f(s[nn][0] - mn0); ls0 += s[nn][0];
            s[nn][1] = ex2f(s[nn][1] - mn0); ls0 += s[nn][1];
            s[nn][2] = ex2f(s[nn][2] - mn1); ls1 += s[nn][2];
            s[nn][3] = ex2f(s[nn][3] - mn1); ls1 += s[nn][3];
        }

        const bool changed = (mn0 != old0) || (mn1 != old1);
        if (__any_sync(0xffffffffu, changed)) {
            const float c0 = ex2f(old0 - mn0);
            const float c1 = ex2f(old1 - mn1);
            sAcc0 = sAcc0 * c0 + ls0;
            sAcc1 = sAcc1 * c1 + ls1;
#pragma unroll
            for (int nn = 0; nn < 8; nn++) {
                o[nn][0] *= c0; o[nn][1] *= c0;
                o[nn][2] *= c1; o[nn][3] *= c1;
            }
        } else {
            sAcc0 += ls0;
            sAcc1 += ls1;
        }

        // ---- O += P.V over 128 keys (fp16) ----
#pragma unroll
        for (int ks = 0; ks < 8; ks++) {
            unsigned pa[4];
            pa[0] = packh2(s[2*ks][0],   s[2*ks][1]);
            pa[1] = packh2(s[2*ks][2],   s[2*ks][3]);
            pa[2] = packh2(s[2*ks+1][0], s[2*ks+1][1]);
            pa[3] = packh2(s[2*ks+1][2], s[2*ks+1][3]);
#pragma unroll
            for (int np = 0; np < 4; np++) {
                const int vr = ks * 16 + vrow_b;
                unsigned off = (unsigned)(vr * 128)
                             + (((unsigned)(np * 32) + vcolb) ^ (((unsigned)(vr & 7)) << 4));
                unsigned vf[4];
                ldsm4t(vf[0], vf[1], vf[2], vf[3], stg + 16384 + off);
                mma_f16(o[2*np],   pa, vf[0], vf[1]);
                mma_f16(o[2*np+1], pa, vf[2], vf[3]);
            }
        }
    }

    // ---- final cross-lane sum reduction ----
    float sL0 = sAcc0, sL1 = sAcc1;
    sL0 += __shfl_xor_sync(0xffffffffu, sL0, 1);
    sL0 += __shfl_xor_sync(0xffffffffu, sL0, 2);
    sL1 += __shfl_xor_sync(0xffffffffu, sL1, 1);
    sL1 += __shfl_xor_sync(0xffffffffu, sL1, 2);

    // ---- normalize + emit fp16 into g_AOh ----
    const float inv0 = 1.f / sL0, inv1 = 1.f / sL1;
    const int qr = q0 + wid * 16 + (lane >> 2);
    const size_t base0 = ((size_t)(b * SEQ + qr)) * DIM + h * HD;
    const size_t base1 = base0 + (size_t)8 * DIM;
#pragma unroll
    for (int nn = 0; nn < 8; nn++) {
        const int c = nn * 8 + (lane & 3) * 2;
        *(unsigned*)(g_AOh + base0 + c) = packh2(o[nn][0] * inv0, o[nn][1] * inv0);
        *(unsigned*)(g_AOh + base1 + c) = packh2(o[nn][2] * inv1, o[nn][3] * inv1);
    }
}

// ---------------------------------------------------------------------------
extern "C" void kernel_launch(void* const* d_in, const int* in_sizes, int n_in,
                              void* d_out, int out_size)
{
    const float* x     = (const float*)d_in[0];
    const float* mask  = (const float*)d_in[1];
    const float* bias  = (const float*)d_in[2];
    const float* Wqkv  = (const float*)d_in[3];
    const float* bqkv  = (const float*)d_in[4];
    const float* Wout  = (const float*)d_in[5];
    const float* bout  = (const float*)d_in[6];
    float* out = (float*)d_out;

    cudaFuncSetAttribute(mma_gemm_kernel,
                         cudaFuncAttributeMaxDynamicSharedMemorySize, GEMM_SMEM);
    cudaFuncSetAttribute(attn_mma_kernel,
                         cudaFuncAttributeMaxDynamicSharedMemorySize, ATTN_SMEM);

    __half *x16, *w1hi, *w1lo, *w2hi, *w2lo, *aoh;
    cudaGetSymbolAddress((void**)&x16,  g_X16);
    cudaGetSymbolAddress((void**)&w1hi, g_W1hi);
    cudaGetSymbolAddress((void**)&w1lo, g_W1lo);
    cudaGetSymbolAddress((void**)&w2hi, g_W2hi);
    cudaGetSymbolAddress((void**)&w2lo, g_W2lo);
    cudaGetSymbolAddress((void**)&aoh,  g_AOh);

    conv_x16_kernel<<<(MROWS * DIM / 4 + 255) / 256, 256>>>(x, x16,
                                                            MROWS * DIM / 4);
    conv_transpose_kernel<<<dim3(DIM / 32, QKVN / 32), dim3(32, 8)>>>(
        Wqkv, w1hi, w1lo, DIM, QKVN);
    conv_transpose_kernel<<<dim3(DIM / 32, DIM / 32), dim3(32, 8)>>>(
        Wout, w2hi, w2lo, DIM, DIM);
    mb_kernel<<<(BATCH * SEQ * SEQ / 8 + 255) / 256, 256>>>(
        mask, bias, BATCH * SEQ * SEQ / 8);

    mma_gemm_kernel<<<dim3(QKVN / 128, MROWS / 128), 256, GEMM_SMEM>>>(
        x16, w1hi, w1lo, bqkv, nullptr, 1);

    attn_mma_kernel<<<dim3(SEQ / 128, BATCH * NH), 256, ATTN_SMEM>>>();

    mma_gemm_kernel<<<dim3(DIM / 128, MROWS / 128), 256, GEMM_SMEM>>>(
        aoh, w2hi, w2lo, bout, out, 0);
}

// round 11
// speedup vs baseline: 1.0942x; 1.0942x over previous
#include <cuda_runtime.h>
#include <cuda_bf16.h>
#include <cuda_fp16.h>

#define BATCH 2
#define SEQ   2048
#define DIM   1024
#define NH    16
#define HD    64
#define MROWS (BATCH*SEQ)   // 4096
#define QKVN  (3*DIM)       // 3072
#define LOG2E 1.4426950408889634f

// ---------------- scratch (__device__ globals; no runtime allocs) ----------
__device__ __half g_Qh[(size_t)BATCH*NH*SEQ*HD];     // fp16, pre-scaled 0.125*log2e
__device__ __half g_Kh[(size_t)BATCH*NH*SEQ*HD];
__device__ __half g_Vh[(size_t)BATCH*NH*SEQ*HD];
__device__ __half g_X16[(size_t)MROWS*DIM];          // x in fp16
__device__ __half g_W1hi[(size_t)QKVN*DIM];          // Wqkv^T hi/lo fp16
__device__ __half g_W1lo[(size_t)QKVN*DIM];
__device__ __half g_W2hi[(size_t)DIM*DIM];           // Wout^T hi/lo fp16
__device__ __half g_W2lo[(size_t)DIM*DIM];
__device__ __half g_AOh[(size_t)MROWS*DIM];          // attention out fp16
__device__ __half g_MB[(size_t)BATCH*SEQ*SEQ];       // (mask + bias)*log2e (fp16)

// ---------------- helpers ---------------------------------------------------
__device__ __forceinline__ unsigned smem_u32(const void* p) {
    unsigned a;
    asm("{ .reg .u64 t; cvta.to.shared.u64 t, %1; cvt.u32.u64 %0, t; }"
        : "=r"(a) : "l"(p));
    return a;
}
__device__ __forceinline__ void ldsm4(unsigned& r0, unsigned& r1,
                                      unsigned& r2, unsigned& r3, unsigned a) {
    asm volatile("ldmatrix.sync.aligned.m8n8.x4.shared.b16 {%0,%1,%2,%3}, [%4];"
                 : "=r"(r0), "=r"(r1), "=r"(r2), "=r"(r3) : "r"(a));
}
__device__ __forceinline__ void ldsm4t(unsigned& r0, unsigned& r1,
                                       unsigned& r2, unsigned& r3, unsigned a) {
    asm volatile("ldmatrix.sync.aligned.m8n8.x4.trans.shared.b16 {%0,%1,%2,%3}, [%4];"
                 : "=r"(r0), "=r"(r1), "=r"(r2), "=r"(r3) : "r"(a));
}
__device__ __forceinline__ void mma_f16(float* c, const unsigned* a,
                                        unsigned b0, unsigned b1) {
    asm volatile(
        "mma.sync.aligned.m16n8k16.row.col.f32.f16.f16.f32 "
        "{%0,%1,%2,%3}, {%4,%5,%6,%7}, {%8,%9}, {%0,%1,%2,%3};"
        : "+f"(c[0]), "+f"(c[1]), "+f"(c[2]), "+f"(c[3])
        : "r"(a[0]), "r"(a[1]), "r"(a[2]), "r"(a[3]), "r"(b0), "r"(b1));
}
__device__ __forceinline__ void cp16(unsigned dst, const void* src) {
    asm volatile("cp.async.cg.shared.global [%0], [%1], 16;"
                 :: "r"(dst), "l"(src) : "memory");
}
__device__ __forceinline__ void cp_commit() {
    asm volatile("cp.async.commit_group;" ::: "memory");
}
__device__ __forceinline__ unsigned packh2(float a, float b) {
    unsigned r;
    asm("cvt.rn.f16x2.f32 %0, %1, %2;" : "=r"(r) : "f"(b), "f"(a));
    return r;
}
// MUFU 2^t
__device__ __forceinline__ float ex2f(float t) {
    float r;
    asm("ex2.approx.f32 %0, %1;" : "=f"(r) : "f"(t));
    return r;
}
// swizzled offset in a [rows][32 f16] tile (64B rows)
__device__ __forceinline__ unsigned swz64(int row, unsigned colb) {
    return (unsigned)(row * 64) + (colb ^ (((unsigned)(row >> 1) & 3u) << 4));
}

#define GEMM_STAGE 24576            // A 8KB | Bhi 8KB | Blo 8KB
#define GEMM_SMEM  (3*GEMM_STAGE)   // 72 KB

// ---------------------------------------------------------------------------
// conversions
// ---------------------------------------------------------------------------
__global__ __launch_bounds__(256) void conv_x16_kernel(
    const float* __restrict__ src, __half* __restrict__ dst, int n4)
{
    int i = blockIdx.x * 256 + threadIdx.x;
    if (i >= n4) return;
    float4 v = *((const float4*)src + i);
    uint2 o;
    o.x = packh2(v.x, v.y);
    o.y = packh2(v.z, v.w);
    ((uint2*)dst)[i] = o;
}

// transpose + fp16 split: W[K][N] -> T{hi,lo}[N][K]
__global__ void conv_transpose_kernel(
    const float* __restrict__ W, __half* __restrict__ Thi,
    __half* __restrict__ Tlo, int K, int N)
{
    __shared__ float t[32][33];
    const int k0 = blockIdx.x * 32, n0 = blockIdx.y * 32;
    const int tx = threadIdx.x, ty = threadIdx.y;
    for (int i = ty; i < 32; i += 8)
        t[i][tx] = W[(size_t)(k0 + i) * N + n0 + tx];
    __syncthreads();
    for (int i = ty; i < 32; i += 8) {
        float v = t[tx][i];
        __half h = __float2half(v);
        Thi[(size_t)(n0 + i) * K + k0 + tx] = h;
        Tlo[(size_t)(n0 + i) * K + k0 + tx] = __float2half(v - __half2float(h));
    }
}

// combined (mask+bias)*log2e in fp16
__global__ __launch_bounds__(256) void mb_kernel(
    const float* __restrict__ mask, const float* __restrict__ bias, int n8)
{
    int i = blockIdx.x * 256 + threadIdx.x;
    if (i >= n8) return;
    const int per_b = SEQ * SEQ / 8;
    int r = i % per_b;
    float4 m0 = ((const float4*)mask)[r*2+0];
    float4 m1 = ((const float4*)mask)[r*2+1];
    float4 b0 = ((const float4*)bias)[i*2+0];
    float4 b1 = ((const float4*)bias)[i*2+1];
    __half2 o[4];
    o[0] = __floats2half2_rn((m0.x + b0.x) * LOG2E, (m0.y + b0.y) * LOG2E);
    o[1] = __floats2half2_rn((m0.z + b0.z) * LOG2E, (m0.w + b0.w) * LOG2E);
    o[2] = __floats2half2_rn((m1.x + b1.x) * LOG2E, (m1.y + b1.y) * LOG2E);
    o[3] = __floats2half2_rn((m1.z + b1.z) * LOG2E, (m1.w + b1.w) * LOG2E);
    ((uint4*)g_MB)[i] = *(uint4*)o;
}

// ---------------------------------------------------------------------------
// HMMA GEMM: A fp16 single, B fp16 hi+lo split (2 MMAs). BK=32, 3-stage
// single-sync cp.async pipeline, 2 CTAs/SM.
// mode 0: out fp32 + bias. mode 1: emit fp16 Q (scaled 0.125*log2e) / K / V.
// ---------------------------------------------------------------------------
__global__ __launch_bounds__(256, 2) void mma_gemm_kernel(
    const __half* __restrict__ A,
    const __half* __restrict__ Bhi, const __half* __restrict__ Blo,
    const float* __restrict__ bias, float* __restrict__ out, int mode)
{
    extern __shared__ char smraw[];
    const unsigned sbase = smem_u32(smraw);
    const int tid  = threadIdx.x;
    const int wid  = tid >> 5;
    const int lane = tid & 31;
    const int warp_m = wid & 3;
    const int warp_n = wid >> 2;
    const int row_a = blockIdx.y * 128;
    const int col0  = blockIdx.x * 128;

    float acc[2][8][4];
#pragma unroll
    for (int i = 0; i < 2; i++)
#pragma unroll
        for (int j = 0; j < 8; j++)
#pragma unroll
            for (int c = 0; c < 4; c++) acc[i][j][c] = 0.f;

    auto issue = [&](int t) {
        const int k0 = t * 32;
        const unsigned stage = (unsigned)((t % 3) * GEMM_STAGE);
#pragma unroll
        for (int p = 0; p < 3; p++) {
            const __half* src = (p == 0) ? A : (p == 1) ? Bhi : Blo;
            const int rb = (p == 0) ? row_a : col0;
            const unsigned pb = stage + (unsigned)p * 8192u;
#pragma unroll
            for (int i = 0; i < 2; i++) {
                const int e = tid + i * 256;
                const int r = e >> 2, c16 = e & 3;
                cp16(sbase + pb + swz64(r, (unsigned)(c16 * 16)),
                     src + (size_t)(rb + r) * DIM + k0 + c16 * 8);
            }
        }
        cp_commit();
    };

    issue(0); issue(1);

    const int amat = lane >> 3;
    const int arow_l = (lane & 7) + ((amat & 1) << 3);
    const unsigned acolx = (unsigned)((amat >> 1) << 4);
    const int brow_l = (lane & 7) + ((amat >> 1) << 3);
    const unsigned bcolx = (unsigned)((amat & 1) << 4);

    for (int t = 0; t < 32; t++) {
        if (t < 31) asm volatile("cp.async.wait_group 1;" ::: "memory");
        else        asm volatile("cp.async.wait_group 0;" ::: "memory");
        __syncthreads();
        if (t + 2 < 32) issue(t + 2);

        const unsigned stage = sbase + (unsigned)((t % 3) * GEMM_STAGE);
#pragma unroll
        for (int ks = 0; ks < 2; ks++) {
            const unsigned kb = (unsigned)(ks * 32);
            unsigned bh[4][4], bl[4][4];
#pragma unroll
            for (int np = 0; np < 4; np++) {
                const int r = warp_n * 64 + np * 16 + brow_l;
                const unsigned ro = swz64(r, kb + bcolx);
                ldsm4(bh[np][0], bh[np][1], bh[np][2], bh[np][3], stage + 8192 + ro);
                ldsm4(bl[np][0], bl[np][1], bl[np][2], bl[np][3], stage + 16384 + ro);
            }
#pragma unroll
            for (int mf = 0; mf < 2; mf++) {
                const int r = warp_m * 32 + mf * 16 + arow_l;
                const unsigned ro = swz64(r, kb + acolx);
                unsigned af[4];
                ldsm4(af[0], af[1], af[2], af[3], stage + ro);
#pragma unroll
                for (int nn = 0; nn < 8; nn++) {
                    const int np = nn >> 1, hf = (nn & 1) * 2;
                    mma_f16(acc[mf][nn], af, bh[np][hf], bh[np][hf + 1]);
                    mma_f16(acc[mf][nn], af, bl[np][hf], bl[np][hf + 1]);
                }
            }
        }
    }

#pragma unroll
    for (int mf = 0; mf < 2; mf++) {
#pragma unroll
        for (int nn = 0; nn < 8; nn++) {
            const int gc = col0 + warp_n * 64 + nn * 8 + (lane & 3) * 2;
            const int r0 = row_a + warp_m * 32 + mf * 16 + (lane >> 2);
            const float bx = bias[gc], by = bias[gc + 1];
            float2 v0, v1;
            v0.x = acc[mf][nn][0] + bx; v0.y = acc[mf][nn][1] + by;
            v1.x = acc[mf][nn][2] + bx; v1.y = acc[mf][nn][3] + by;
            if (mode == 0) {
                *(float2*)(out + (size_t)r0 * DIM + gc)       = v0;
                *(float2*)(out + (size_t)(r0 + 8) * DIM + gc) = v1;
            } else {
                const int sel = gc >> 10;
                const int w   = gc & 1023;
                const int h   = w >> 6;
                const int d0  = w & 63;
                __half* dst;
                float sc;
                if (sel == 0)      { dst = g_Qh; sc = 0.125f * LOG2E; }
                else if (sel == 1) { dst = g_Kh; sc = 1.f; }
                else               { dst = g_Vh; sc = 1.f; }
                const int b0 = r0 >> 11, s0 = r0 & 2047;
                const int r1 = r0 + 8;
                const int b1 = r1 >> 11, s1 = r1 & 2047;
                const size_t i0 = (((size_t)b0 * NH + h) * SEQ + s0) * HD + d0;
                const size_t i1 = (((size_t)b1 * NH + h) * SEQ + s1) * HD + d0;
                *(unsigned*)(dst + i0) = packh2(v0.x * sc, v0.y * sc);
                *(unsigned*)(dst + i1) = packh2(v1.x * sc, v1.y * sc);
            }
        }
    }
}

// ---------------------------------------------------------------------------
// fp16 flash attention (log2-domain, MUFU exp2). 128 q x 64 k tiles, 8 warps,
// 2 CTAs/SM, 3-stage single-sync pipeline. Mask+bias tiles streamed through
// the cp.async pipeline (smem, prefetched 2 tiles ahead); Q frags in regs.
// Stage layout: K 8KB | V 8KB | MB 16KB = 32KB.
// ---------------------------------------------------------------------------
#define ATTN_STAGE 32768
#define ATTN_SMEM  (16384 + 3*ATTN_STAGE)   // 112 KB -> 2 CTAs = 224 KB/SM

__global__ __launch_bounds__(256, 2) void attn_mma_kernel()
{
    extern __shared__ char smraw[];
    const unsigned sbase = smem_u32(smraw);
    const int tid = threadIdx.x, wid = tid >> 5, lane = tid & 31;
    const int bh = blockIdx.y, b = bh >> 4, h = bh & 15;
    const int q0 = blockIdx.x * 128;

    const __half* Qg = g_Qh + (size_t)bh * SEQ * HD;
    const __half* Kg = g_Kh + (size_t)bh * SEQ * HD;
    const __half* Vg = g_Vh + (size_t)bh * SEQ * HD;
    const __half* MBg = g_MB + (size_t)(b * SEQ + q0) * SEQ;   // [128 q][2048 k]

    // Q tile -> smem (128B rows, 128B swizzle), own commit group
#pragma unroll
    for (int i = 0; i < 4; i++) {
        const int e = tid + i * 256;
        const int r = e >> 3, c4 = e & 7;
        unsigned off = (unsigned)(r * 128 + c4 * 16);
        off ^= (off >> 3) & 0x70;
        cp16(sbase + off, Qg + (size_t)(q0 + r) * HD + c4 * 8);
    }
    cp_commit();

    // stage: K (64 rows x 128B) | V (64 rows x 128B) | MB (128 q rows x 128B)
    auto issue = [&](int t) {
        const int k0 = t * 64;
        const unsigned stg = 16384u + (unsigned)((t % 3) * ATTN_STAGE);
#pragma unroll
        for (int p = 0; p < 2; p++) {
            const __half* src = p ? Vg : Kg;
#pragma unroll
            for (int i = 0; i < 2; i++) {
                const int e = tid + i * 256;
                const int r = e >> 3, c4 = e & 7;
                unsigned off = (unsigned)(r * 128 + c4 * 16);
                off ^= (off >> 3) & 0x70;
                cp16(sbase + stg + (unsigned)p * 8192u + off,
                     src + (size_t)(k0 + r) * HD + c4 * 8);
            }
        }
#pragma unroll
        for (int i = 0; i < 4; i++) {
            const int e = tid + i * 256;            // 0..1023
            const int r = e >> 3, c4 = e & 7;       // q row, 16B unit
            unsigned off = (unsigned)(r * 128 + c4 * 16);
            off ^= (off >> 3) & 0x70;
            cp16(sbase + stg + 16384u + off,
                 MBg + (size_t)r * SEQ + k0 + c4 * 8);
        }
        cp_commit();
    };
    issue(0); issue(1);

    const int amat = lane >> 3;
    const int arow = wid * 16 + (lane & 7) + ((amat & 1) << 3);
    const unsigned acolx = (unsigned)((amat >> 1) << 4);
    const int krow_b = (lane & 7) + ((amat >> 1) << 3);
    const unsigned kcolx = (unsigned)((amat & 1) << 4);
    const int vrow_b = (lane & 7) + ((amat & 1) << 3);
    const unsigned vcolb = (unsigned)((lane >> 4) << 4);

    // per-thread mask rows within the 128-row MB tile
    const int qr0 = wid * 16 + (lane >> 2);        // row 0 of this thread
    const unsigned mb_l = (unsigned)((lane & 3) * 4);

    float o[8][4];
#pragma unroll
    for (int nn = 0; nn < 8; nn++)
#pragma unroll
        for (int c = 0; c < 4; c++) o[nn][c] = 0.f;
    float sM0 = -1e30f, sM1 = -1e30f, sAcc0 = 0.f, sAcc1 = 0.f;

    unsigned qf[4][4];   // Q fragments, loaded once

    for (int t = 0; t < 32; t++) {
        if (t < 31) asm volatile("cp.async.wait_group 1;" ::: "memory");
        else        asm volatile("cp.async.wait_group 0;" ::: "memory");
        __syncthreads();
        if (t + 2 < 32) issue(t + 2);

        const unsigned stg = sbase + 16384u + (unsigned)((t % 3) * ATTN_STAGE);

        if (t == 0) {
#pragma unroll
            for (int ks = 0; ks < 4; ks++) {
                unsigned qoff = (unsigned)(arow * 128)
                              + (((unsigned)(ks * 32) + acolx) ^ (((unsigned)(arow & 7)) << 4));
                ldsm4(qf[ks][0], qf[ks][1], qf[ks][2], qf[ks][3], sbase + qoff);
            }
        }

        // ---- S = Q.K^T (fp16, log2-domain) ----
        float s[8][4];
#pragma unroll
        for (int nn = 0; nn < 8; nn++)
#pragma unroll
            for (int c = 0; c < 4; c++) s[nn][c] = 0.f;
#pragma unroll
        for (int ks = 0; ks < 4; ks++) {
#pragma unroll
            for (int np = 0; np < 4; np++) {
                const int kr = np * 16 + krow_b;
                unsigned off = (unsigned)(kr * 128)
                             + (((unsigned)(ks * 32) + kcolx) ^ (((unsigned)(kr & 7)) << 4));
                unsigned kf[4];
                ldsm4(kf[0], kf[1], kf[2], kf[3], stg + off);
                mma_f16(s[2*np],   qf[ks], kf[0], kf[1]);
                mma_f16(s[2*np+1], qf[ks], kf[2], kf[3]);
            }
        }

        // ---- + (mask+bias)*log2e from smem MB tile ----
        const unsigned mb0 = stg + 16384u + (unsigned)(qr0 * 128) + mb_l;
        const unsigned mb1 = mb0 + 8u * 128u;
        const unsigned sw0 = ((unsigned)(qr0 & 7)) << 4;
        const unsigned sw1 = ((unsigned)((qr0 + 8) & 7)) << 4;
#pragma unroll
        for (int nn = 0; nn < 8; nn++) {
            const unsigned u = (unsigned)(nn * 16);
            __half2 h0 = *(__half2*)(smraw + (mb0 + (u ^ sw0)) - sbase);
            __half2 h1 = *(__half2*)(smraw + (mb1 + (u ^ sw1)) - sbase);
            float2 f0 = __half22float2(h0);
            float2 f1 = __half22float2(h1);
            s[nn][0] += f0.x; s[nn][1] += f0.y;
            s[nn][2] += f1.x; s[nn][3] += f1.y;
        }

        // ---- online softmax (log2-domain, MUFU exp2) ----
        float mx0 = -1e30f, mx1 = -1e30f;
#pragma unroll
        for (int nn = 0; nn < 8; nn++) {
            mx0 = fmaxf(mx0, fmaxf(s[nn][0], s[nn][1]));
            mx1 = fmaxf(mx1, fmaxf(s[nn][2], s[nn][3]));
        }
        mx0 = fmaxf(mx0, __shfl_xor_sync(0xffffffffu, mx0, 1));
        mx0 = fmaxf(mx0, __shfl_xor_sync(0xffffffffu, mx0, 2));
        mx1 = fmaxf(mx1, __shfl_xor_sync(0xffffffffu, mx1, 1));
        mx1 = fmaxf(mx1, __shfl_xor_sync(0xffffffffu, mx1, 2));
        const float old0 = sM0, old1 = sM1;
        const float mn0 = fmaxf(sM0, mx0), mn1 = fmaxf(sM1, mx1);
        sM0 = mn0; sM1 = mn1;

        float ls0 = 0.f, ls1 = 0.f;
#pragma unroll
        for (int nn = 0; nn < 8; nn++) {
            s[nn][0] = ex2f(s[nn][0] - mn0); ls0 += s[nn][0];
            s[nn][1] = ex2f(s[nn][1] - mn0); ls0 += s[nn][1];
            s[nn][2] = ex2f(s[nn][2] - mn1); ls1 += s[nn][2];
            s[nn][3] = ex2f(s[nn][3] - mn1); ls1 += s[nn][3];
        }

        const bool changed = (mn0 != old0) || (mn1 != old1);
        if (__any_sync(0xffffffffu, changed)) {
            const float c0 = ex2f(old0 - mn0);
            const float c1 = ex2f(old1 - mn1);
            sAcc0 = sAcc0 * c0 + ls0;
            sAcc1 = sAcc1 * c1 + ls1;
#pragma unroll
            for (int nn = 0; nn < 8; nn++) {
                o[nn][0] *= c0; o[nn][1] *= c0;
                o[nn][2] *= c1; o[nn][3] *= c1;
            }
        } else {
            sAcc0 += ls0;
            sAcc1 += ls1;
        }

        // ---- O += P.V (fp16) ----
#pragma unroll
        for (int ks = 0; ks < 4; ks++) {
            unsigned pa[4];
            pa[0] = packh2(s[2*ks][0],   s[2*ks][1]);
            pa[1] = packh2(s[2*ks][2],   s[2*ks][3]);
            pa[2] = packh2(s[2*ks+1][0], s[2*ks+1][1]);
            pa[3] = packh2(s[2*ks+1][2], s[2*ks+1][3]);
#pragma unroll
            for (int np = 0; np < 4; np++) {
                const int vr = ks * 16 + vrow_b;
                unsigned off = (unsigned)(vr * 128)
                             + (((unsigned)(np * 32) + vcolb) ^ (((unsigned)(vr & 7)) << 4));
                unsigned vf[4];
                ldsm4t(vf[0], vf[1], vf[2], vf[3], stg + 8192 + off);
                mma_f16(o[2*np],   pa, vf[0], vf[1]);
                mma_f16(o[2*np+1], pa, vf[2], vf[3]);
            }
        }
    }

    // ---- final cross-lane sum reduction ----
    float sL0 = sAcc0, sL1 = sAcc1;
    sL0 += __shfl_xor_sync(0xffffffffu, sL0, 1);
    sL0 += __shfl_xor_sync(0xffffffffu, sL0, 2);
    sL1 += __shfl_xor_sync(0xffffffffu, sL1, 1);
    sL1 += __shfl_xor_sync(0xffffffffu, sL1, 2);

    // ---- normalize + emit fp16 into g_AOh ----
    const float inv0 = 1.f / sL0, inv1 = 1.f / sL1;
    const int qr = q0 + wid * 16 + (lane >> 2);
    const size_t base0 = ((size_t)(b * SEQ + qr)) * DIM + h * HD;
    const size_t base1 = base0 + (size_t)8 * DIM;
#pragma unroll
    for (int nn = 0; nn < 8; nn++) {
        const int c = nn * 8 + (lane & 3) * 2;
        *(unsigned*)(g_AOh + base0 + c) = packh2(o[nn][0] * inv0, o[nn][1] * inv0);
        *(unsigned*)(g_AOh + base1 + c) = packh2(o[nn][2] * inv1, o[nn][3] * inv1);
    }
}

// ---------------------------------------------------------------------------
extern "C" void kernel_launch(void* const* d_in, const int* in_sizes, int n_in,
                              void* d_out, int out_size)
{
    const float* x     = (const float*)d_in[0];
    const float* mask  = (const float*)d_in[1];
    const float* bias  = (const float*)d_in[2];
    const float* Wqkv  = (const float*)d_in[3];
    const float* bqkv  = (const float*)d_in[4];
    const float* Wout  = (const float*)d_in[5];
    const float* bout  = (const float*)d_in[6];
    float* out = (float*)d_out;

    cudaFuncSetAttribute(mma_gemm_kernel,
                         cudaFuncAttributeMaxDynamicSharedMemorySize, GEMM_SMEM);
    cudaFuncSetAttribute(attn_mma_kernel,
                         cudaFuncAttributeMaxDynamicSharedMemorySize, ATTN_SMEM);

    __half *x16, *w1hi, *w1lo, *w2hi, *w2lo, *aoh;
    cudaGetSymbolAddress((void**)&x16,  g_X16);
    cudaGetSymbolAddress((void**)&w1hi, g_W1hi);
    cudaGetSymbolAddress((void**)&w1lo, g_W1lo);
    cudaGetSymbolAddress((void**)&w2hi, g_W2hi);
    cudaGetSymbolAddress((void**)&w2lo, g_W2lo);
    cudaGetSymbolAddress((void**)&aoh,  g_AOh);

    conv_x16_kernel<<<(MROWS * DIM / 4 + 255) / 256, 256>>>(x, x16,
                                                            MROWS * DIM / 4);
    conv_transpose_kernel<<<dim3(DIM / 32, QKVN / 32), dim3(32, 8)>>>(
        Wqkv, w1hi, w1lo, DIM, QKVN);
    conv_transpose_kernel<<<dim3(DIM / 32, DIM / 32), dim3(32, 8)>>>(
        Wout, w2hi, w2lo, DIM, DIM);
    mb_kernel<<<(BATCH * SEQ * SEQ / 8 + 255) / 256, 256>>>(
        mask, bias, BATCH * SEQ * SEQ / 8);

    mma_gemm_kernel<<<dim3(QKVN / 128, MROWS / 128), 256, GEMM_SMEM>>>(
        x16, w1hi, w1lo, bqkv, nullptr, 1);

    attn_mma_kernel<<<dim3(SEQ / 128, BATCH * NH), 256, ATTN_SMEM>>>();

    mma_gemm_kernel<<<dim3(DIM / 128, MROWS / 128), 256, GEMM_SMEM>>>(
        aoh, w2hi, w2lo, bout, out, 0);
}

// round 12
// speedup vs baseline: 1.2994x; 1.1876x over previous
#include <cuda_runtime.h>
#include <cuda_bf16.h>
#include <cuda_fp16.h>

#define BATCH 2
#define SEQ   2048
#define DIM   1024
#define NH    16
#define HD    64
#define MROWS (BATCH*SEQ)   // 4096
#define QKVN  (3*DIM)       // 3072
#define LOG2E 1.4426950408889634f

// ---------------- scratch (__device__ globals; no runtime allocs) ----------
__device__ __half g_Qh[(size_t)BATCH*NH*SEQ*HD];     // fp16, pre-scaled 0.125*log2e
__device__ __half g_Kh[(size_t)BATCH*NH*SEQ*HD];
__device__ __half g_Vh[(size_t)BATCH*NH*SEQ*HD];
__device__ __half g_X16[(size_t)MROWS*DIM];          // x in fp16
__device__ __half g_W1h[(size_t)QKVN*DIM];           // Wqkv^T fp16 (single)
__device__ __half g_W2hi[(size_t)DIM*DIM];           // Wout^T hi/lo fp16
__device__ __half g_W2lo[(size_t)DIM*DIM];
__device__ __half g_AOh[(size_t)MROWS*DIM];          // attention out fp16
__device__ __half g_MB[(size_t)BATCH*SEQ*SEQ];       // (mask + bias)*log2e (fp16)

// ---------------- helpers ---------------------------------------------------
__device__ __forceinline__ unsigned smem_u32(const void* p) {
    unsigned a;
    asm("{ .reg .u64 t; cvta.to.shared.u64 t, %1; cvt.u32.u64 %0, t; }"
        : "=r"(a) : "l"(p));
    return a;
}
__device__ __forceinline__ void ldsm4(unsigned& r0, unsigned& r1,
                                      unsigned& r2, unsigned& r3, unsigned a) {
    asm volatile("ldmatrix.sync.aligned.m8n8.x4.shared.b16 {%0,%1,%2,%3}, [%4];"
                 : "=r"(r0), "=r"(r1), "=r"(r2), "=r"(r3) : "r"(a));
}
__device__ __forceinline__ void ldsm4t(unsigned& r0, unsigned& r1,
                                       unsigned& r2, unsigned& r3, unsigned a) {
    asm volatile("ldmatrix.sync.aligned.m8n8.x4.trans.shared.b16 {%0,%1,%2,%3}, [%4];"
                 : "=r"(r0), "=r"(r1), "=r"(r2), "=r"(r3) : "r"(a));
}
__device__ __forceinline__ void mma_f16(float* c, const unsigned* a,
                                        unsigned b0, unsigned b1) {
    asm volatile(
        "mma.sync.aligned.m16n8k16.row.col.f32.f16.f16.f32 "
        "{%0,%1,%2,%3}, {%4,%5,%6,%7}, {%8,%9}, {%0,%1,%2,%3};"
        : "+f"(c[0]), "+f"(c[1]), "+f"(c[2]), "+f"(c[3])
        : "r"(a[0]), "r"(a[1]), "r"(a[2]), "r"(a[3]), "r"(b0), "r"(b1));
}
__device__ __forceinline__ void cp16(unsigned dst, const void* src) {
    asm volatile("cp.async.cg.shared.global [%0], [%1], 16;"
                 :: "r"(dst), "l"(src) : "memory");
}
__device__ __forceinline__ void cp_commit() {
    asm volatile("cp.async.commit_group;" ::: "memory");
}
__device__ __forceinline__ unsigned packh2(float a, float b) {
    unsigned r;
    asm("cvt.rn.f16x2.f32 %0, %1, %2;" : "=r"(r) : "f"(b), "f"(a));
    return r;
}
// MUFU 2^t
__device__ __forceinline__ float ex2f(float t) {
    float r;
    asm("ex2.approx.f32 %0, %1;" : "=f"(r) : "f"(t));
    return r;
}
// swizzled offset in a [rows][32 f16] tile (64B rows)
__device__ __forceinline__ unsigned swz64(int row, unsigned colb) {
    return (unsigned)(row * 64) + (colb ^ (((unsigned)(row >> 1) & 3u) << 4));
}

#define GEMM_STAGE 24576            // A 8KB | Bhi 8KB | (Blo 8KB)
#define GEMM_SMEM  (3*GEMM_STAGE)   // 72 KB

// ---------------------------------------------------------------------------
// conversions
// ---------------------------------------------------------------------------
__global__ __launch_bounds__(256) void conv_x16_kernel(
    const float* __restrict__ src, __half* __restrict__ dst, int n4)
{
    int i = blockIdx.x * 256 + threadIdx.x;
    if (i >= n4) return;
    float4 v = *((const float4*)src + i);
    uint2 o;
    o.x = packh2(v.x, v.y);
    o.y = packh2(v.z, v.w);
    ((uint2*)dst)[i] = o;
}

// transpose + fp16 (optional lo split): W[K][N] -> T{hi[,lo]}[N][K]
__global__ void conv_transpose_kernel(
    const float* __restrict__ W, __half* __restrict__ Thi,
    __half* __restrict__ Tlo, int K, int N)
{
    __shared__ float t[32][33];
    const int k0 = blockIdx.x * 32, n0 = blockIdx.y * 32;
    const int tx = threadIdx.x, ty = threadIdx.y;
    for (int i = ty; i < 32; i += 8)
        t[i][tx] = W[(size_t)(k0 + i) * N + n0 + tx];
    __syncthreads();
    for (int i = ty; i < 32; i += 8) {
        float v = t[tx][i];
        __half h = __float2half(v);
        Thi[(size_t)(n0 + i) * K + k0 + tx] = h;
        if (Tlo)
            Tlo[(size_t)(n0 + i) * K + k0 + tx] = __float2half(v - __half2float(h));
    }
}

// combined (mask+bias)*log2e in fp16
__global__ __launch_bounds__(256) void mb_kernel(
    const float* __restrict__ mask, const float* __restrict__ bias, int n8)
{
    int i = blockIdx.x * 256 + threadIdx.x;
    if (i >= n8) return;
    const int per_b = SEQ * SEQ / 8;
    int r = i % per_b;
    float4 m0 = ((const float4*)mask)[r*2+0];
    float4 m1 = ((const float4*)mask)[r*2+1];
    float4 b0 = ((const float4*)bias)[i*2+0];
    float4 b1 = ((const float4*)bias)[i*2+1];
    __half2 o[4];
    o[0] = __floats2half2_rn((m0.x + b0.x) * LOG2E, (m0.y + b0.y) * LOG2E);
    o[1] = __floats2half2_rn((m0.z + b0.z) * LOG2E, (m0.w + b0.w) * LOG2E);
    o[2] = __floats2half2_rn((m1.x + b1.x) * LOG2E, (m1.y + b1.y) * LOG2E);
    o[3] = __floats2half2_rn((m1.z + b1.z) * LOG2E, (m1.w + b1.w) * LOG2E);
    ((uint4*)g_MB)[i] = *(uint4*)o;
}

// ---------------------------------------------------------------------------
// HMMA GEMM: A fp16 single; B fp16 single (SPLIT=false) or hi+lo (SPLIT=true).
// BK=32, 3-stage single-sync cp.async pipeline, 2 CTAs/SM.
// mode 0: out fp32 + bias. mode 1: emit fp16 Q (scaled 0.125*log2e) / K / V.
// ---------------------------------------------------------------------------
template<bool SPLIT>
__global__ __launch_bounds__(256, 2) void mma_gemm_kernel(
    const __half* __restrict__ A,
    const __half* __restrict__ Bhi, const __half* __restrict__ Blo,
    const float* __restrict__ bias, float* __restrict__ out, int mode)
{
    extern __shared__ char smraw[];
    const unsigned sbase = smem_u32(smraw);
    const int tid  = threadIdx.x;
    const int wid  = tid >> 5;
    const int lane = tid & 31;
    const int warp_m = wid & 3;
    const int warp_n = wid >> 2;
    const int row_a = blockIdx.y * 128;
    const int col0  = blockIdx.x * 128;

    float acc[2][8][4];
#pragma unroll
    for (int i = 0; i < 2; i++)
#pragma unroll
        for (int j = 0; j < 8; j++)
#pragma unroll
            for (int c = 0; c < 4; c++) acc[i][j][c] = 0.f;

    auto issue = [&](int t) {
        const int k0 = t * 32;
        const unsigned stage = (unsigned)((t % 3) * GEMM_STAGE);
        const int NP = SPLIT ? 3 : 2;
#pragma unroll
        for (int p = 0; p < NP; p++) {
            const __half* src = (p == 0) ? A : (p == 1) ? Bhi : Blo;
            const int rb = (p == 0) ? row_a : col0;
            const unsigned pb = stage + (unsigned)p * 8192u;
#pragma unroll
            for (int i = 0; i < 2; i++) {
                const int e = tid + i * 256;
                const int r = e >> 2, c16 = e & 3;
                cp16(sbase + pb + swz64(r, (unsigned)(c16 * 16)),
                     src + (size_t)(rb + r) * DIM + k0 + c16 * 8);
            }
        }
        cp_commit();
    };

    issue(0); issue(1);

    const int amat = lane >> 3;
    const int arow_l = (lane & 7) + ((amat & 1) << 3);
    const unsigned acolx = (unsigned)((amat >> 1) << 4);
    const int brow_l = (lane & 7) + ((amat >> 1) << 3);
    const unsigned bcolx = (unsigned)((amat & 1) << 4);

    for (int t = 0; t < 32; t++) {
        if (t < 31) asm volatile("cp.async.wait_group 1;" ::: "memory");
        else        asm volatile("cp.async.wait_group 0;" ::: "memory");
        __syncthreads();
        if (t + 2 < 32) issue(t + 2);

        const unsigned stage = sbase + (unsigned)((t % 3) * GEMM_STAGE);
#pragma unroll
        for (int ks = 0; ks < 2; ks++) {
            const unsigned kb = (unsigned)(ks * 32);
            unsigned bh[4][4], bl[4][4];
#pragma unroll
            for (int np = 0; np < 4; np++) {
                const int r = warp_n * 64 + np * 16 + brow_l;
                const unsigned ro = swz64(r, kb + bcolx);
                ldsm4(bh[np][0], bh[np][1], bh[np][2], bh[np][3], stage + 8192 + ro);
                if (SPLIT)
                    ldsm4(bl[np][0], bl[np][1], bl[np][2], bl[np][3], stage + 16384 + ro);
            }
#pragma unroll
            for (int mf = 0; mf < 2; mf++) {
                const int r = warp_m * 32 + mf * 16 + arow_l;
                const unsigned ro = swz64(r, kb + acolx);
                unsigned af[4];
                ldsm4(af[0], af[1], af[2], af[3], stage + ro);
#pragma unroll
                for (int nn = 0; nn < 8; nn++) {
                    const int np = nn >> 1, hf = (nn & 1) * 2;
                    mma_f16(acc[mf][nn], af, bh[np][hf], bh[np][hf + 1]);
                    if (SPLIT)
                        mma_f16(acc[mf][nn], af, bl[np][hf], bl[np][hf + 1]);
                }
            }
        }
    }

#pragma unroll
    for (int mf = 0; mf < 2; mf++) {
#pragma unroll
        for (int nn = 0; nn < 8; nn++) {
            const int gc = col0 + warp_n * 64 + nn * 8 + (lane & 3) * 2;
            const int r0 = row_a + warp_m * 32 + mf * 16 + (lane >> 2);
            const float bx = bias[gc], by = bias[gc + 1];
            float2 v0, v1;
            v0.x = acc[mf][nn][0] + bx; v0.y = acc[mf][nn][1] + by;
            v1.x = acc[mf][nn][2] + bx; v1.y = acc[mf][nn][3] + by;
            if (mode == 0) {
                *(float2*)(out + (size_t)r0 * DIM + gc)       = v0;
                *(float2*)(out + (size_t)(r0 + 8) * DIM + gc) = v1;
            } else {
                const int sel = gc >> 10;
                const int w   = gc & 1023;
                const int h   = w >> 6;
                const int d0  = w & 63;
                __half* dst;
                float sc;
                if (sel == 0)      { dst = g_Qh; sc = 0.125f * LOG2E; }
                else if (sel == 1) { dst = g_Kh; sc = 1.f; }
                else               { dst = g_Vh; sc = 1.f; }
                const int b0 = r0 >> 11, s0 = r0 & 2047;
                const int r1 = r0 + 8;
                const int b1 = r1 >> 11, s1 = r1 & 2047;
                const size_t i0 = (((size_t)b0 * NH + h) * SEQ + s0) * HD + d0;
                const size_t i1 = (((size_t)b1 * NH + h) * SEQ + s1) * HD + d0;
                *(unsigned*)(dst + i0) = packh2(v0.x * sc, v0.y * sc);
                *(unsigned*)(dst + i1) = packh2(v1.x * sc, v1.y * sc);
            }
        }
    }
}

// ---------------------------------------------------------------------------
// fp16 flash attention (log2-domain, MUFU exp2). 128 q x 64 k tiles, 8 warps,
// 2 CTAs/SM, 3-stage single-sync pipeline. Mask+bias streamed through the
// cp.async pipeline; Q fragments hoisted to registers.
// Stage layout: K 8KB | V 8KB | MB 16KB = 32KB.
// ---------------------------------------------------------------------------
#define ATTN_STAGE 32768
#define ATTN_SMEM  (16384 + 3*ATTN_STAGE)   // 112 KB -> 2 CTAs = 224 KB/SM

__global__ __launch_bounds__(256, 2) void attn_mma_kernel()
{
    extern __shared__ char smraw[];
    const unsigned sbase = smem_u32(smraw);
    const int tid = threadIdx.x, wid = tid >> 5, lane = tid & 31;
    const int bh = blockIdx.y, b = bh >> 4, h = bh & 15;
    const int q0 = blockIdx.x * 128;

    const __half* Qg = g_Qh + (size_t)bh * SEQ * HD;
    const __half* Kg = g_Kh + (size_t)bh * SEQ * HD;
    const __half* Vg = g_Vh + (size_t)bh * SEQ * HD;
    const __half* MBg = g_MB + (size_t)(b * SEQ + q0) * SEQ;   // [128 q][2048 k]

    // Q tile -> smem (128B rows, 128B swizzle), own commit group
#pragma unroll
    for (int i = 0; i < 4; i++) {
        const int e = tid + i * 256;
        const int r = e >> 3, c4 = e & 7;
        unsigned off = (unsigned)(r * 128 + c4 * 16);
        off ^= (off >> 3) & 0x70;
        cp16(sbase + off, Qg + (size_t)(q0 + r) * HD + c4 * 8);
    }
    cp_commit();

    // stage: K (64 rows x 128B) | V (64 rows x 128B) | MB (128 q rows x 128B)
    auto issue = [&](int t) {
        const int k0 = t * 64;
        const unsigned stg = 16384u + (unsigned)((t % 3) * ATTN_STAGE);
#pragma unroll
        for (int p = 0; p < 2; p++) {
            const __half* src = p ? Vg : Kg;
#pragma unroll
            for (int i = 0; i < 2; i++) {
                const int e = tid + i * 256;
                const int r = e >> 3, c4 = e & 7;
                unsigned off = (unsigned)(r * 128 + c4 * 16);
                off ^= (off >> 3) & 0x70;
                cp16(sbase + stg + (unsigned)p * 8192u + off,
                     src + (size_t)(k0 + r) * HD + c4 * 8);
            }
        }
#pragma unroll
        for (int i = 0; i < 4; i++) {
            const int e = tid + i * 256;            // 0..1023
            const int r = e >> 3, c4 = e & 7;       // q row, 16B unit
            unsigned off = (unsigned)(r * 128 + c4 * 16);
            off ^= (off >> 3) & 0x70;
            cp16(sbase + stg + 16384u + off,
                 MBg + (size_t)r * SEQ + k0 + c4 * 8);
        }
        cp_commit();
    };
    issue(0); issue(1);

    const int amat = lane >> 3;
    const int arow = wid * 16 + (lane & 7) + ((amat & 1) << 3);
    const unsigned acolx = (unsigned)((amat >> 1) << 4);
    const int krow_b = (lane & 7) + ((amat >> 1) << 3);
    const unsigned kcolx = (unsigned)((amat & 1) << 4);
    const int vrow_b = (lane & 7) + ((amat & 1) << 3);
    const unsigned vcolb = (unsigned)((lane >> 4) << 4);

    const int qr0 = wid * 16 + (lane >> 2);
    const unsigned mb_l = (unsigned)((lane & 3) * 4);

    float o[8][4];
#pragma unroll
    for (int nn = 0; nn < 8; nn++)
#pragma unroll
        for (int c = 0; c < 4; c++) o[nn][c] = 0.f;
    float sM0 = -1e30f, sM1 = -1e30f, sAcc0 = 0.f, sAcc1 = 0.f;

    unsigned qf[4][4];   // Q fragments, loaded once

    for (int t = 0; t < 32; t++) {
        if (t < 31) asm volatile("cp.async.wait_group 1;" ::: "memory");
        else        asm volatile("cp.async.wait_group 0;" ::: "memory");
        __syncthreads();
        if (t + 2 < 32) issue(t + 2);

        const unsigned stg = sbase + 16384u + (unsigned)((t % 3) * ATTN_STAGE);

        if (t == 0) {
#pragma unroll
            for (int ks = 0; ks < 4; ks++) {
                unsigned qoff = (unsigned)(arow * 128)
                              + (((unsigned)(ks * 32) + acolx) ^ (((unsigned)(arow & 7)) << 4));
                ldsm4(qf[ks][0], qf[ks][1], qf[ks][2], qf[ks][3], sbase + qoff);
            }
        }

        // ---- S = Q.K^T (fp16, log2-domain) ----
        float s[8][4];
#pragma unroll
        for (int nn = 0; nn < 8; nn++)
#pragma unroll
            for (int c = 0; c < 4; c++) s[nn][c] = 0.f;
#pragma unroll
        for (int ks = 0; ks < 4; ks++) {
#pragma unroll
            for (int np = 0; np < 4; np++) {
                const int kr = np * 16 + krow_b;
                unsigned off = (unsigned)(kr * 128)
                             + (((unsigned)(ks * 32) + kcolx) ^ (((unsigned)(kr & 7)) << 4));
                unsigned kf[4];
                ldsm4(kf[0], kf[1], kf[2], kf[3], stg + off);
                mma_f16(s[2*np],   qf[ks], kf[0], kf[1]);
                mma_f16(s[2*np+1], qf[ks], kf[2], kf[3]);
            }
        }

        // ---- + (mask+bias)*log2e from smem MB tile ----
        const unsigned mb0 = stg + 16384u + (unsigned)(qr0 * 128) + mb_l;
        const unsigned mb1 = mb0 + 8u * 128u;
        const unsigned sw0 = ((unsigned)(qr0 & 7)) << 4;
        const unsigned sw1 = ((unsigned)((qr0 + 8) & 7)) << 4;
#pragma unroll
        for (int nn = 0; nn < 8; nn++) {
            const unsigned u = (unsigned)(nn * 16);
            __half2 h0 = *(__half2*)(smraw + (mb0 + (u ^ sw0)) - sbase);
            __half2 h1 = *(__half2*)(smraw + (mb1 + (u ^ sw1)) - sbase);
            float2 f0 = __half22float2(h0);
            float2 f1 = __half22float2(h1);
            s[nn][0] += f0.x; s[nn][1] += f0.y;
            s[nn][2] += f1.x; s[nn][3] += f1.y;
        }

        // ---- online softmax (log2-domain, MUFU exp2) ----
        float mx0 = -1e30f, mx1 = -1e30f;
#pragma unroll
        for (int nn = 0; nn < 8; nn++) {
            mx0 = fmaxf(mx0, fmaxf(s[nn][0], s[nn][1]));
            mx1 = fmaxf(mx1, fmaxf(s[nn][2], s[nn][3]));
        }
        mx0 = fmaxf(mx0, __shfl_xor_sync(0xffffffffu, mx0, 1));
        mx0 = fmaxf(mx0, __shfl_xor_sync(0xffffffffu, mx0, 2));
        mx1 = fmaxf(mx1, __shfl_xor_sync(0xffffffffu, mx1, 1));
        mx1 = fmaxf(mx1, __shfl_xor_sync(0xffffffffu, mx1, 2));
        const float old0 = sM0, old1 = sM1;
        const float mn0 = fmaxf(sM0, mx0), mn1 = fmaxf(sM1, mx1);
        sM0 = mn0; sM1 = mn1;

        float ls0 = 0.f, ls1 = 0.f;
#pragma unroll
        for (int nn = 0; nn < 8; nn++) {
            s[nn][0] = ex2f(s[nn][0] - mn0); ls0 += s[nn][0];
            s[nn][1] = ex2f(s[nn][1] - mn0); ls0 += s[nn][1];
            s[nn][2] = ex2f(s[nn][2] - mn1); ls1 += s[nn][2];
            s[nn][3] = ex2f(s[nn][3] - mn1); ls1 += s[nn][3];
        }

        const bool changed = (mn0 != old0) || (mn1 != old1);
        if (__any_sync(0xffffffffu, changed)) {
            const float c0 = ex2f(old0 - mn0);
            const float c1 = ex2f(old1 - mn1);
            sAcc0 = sAcc0 * c0 + ls0;
            sAcc1 = sAcc1 * c1 + ls1;
#pragma unroll
            for (int nn = 0; nn < 8; nn++) {
                o[nn][0] *= c0; o[nn][1] *= c0;
                o[nn][2] *= c1; o[nn][3] *= c1;
            }
        } else {
            sAcc0 += ls0;
            sAcc1 += ls1;
        }

        // ---- O += P.V (fp16) ----
#pragma unroll
        for (int ks = 0; ks < 4; ks++) {
            unsigned pa[4];
            pa[0] = packh2(s[2*ks][0],   s[2*ks][1]);
            pa[1] = packh2(s[2*ks][2],   s[2*ks][3]);
            pa[2] = packh2(s[2*ks+1][0], s[2*ks+1][1]);
            pa[3] = packh2(s[2*ks+1][2], s[2*ks+1][3]);
#pragma unroll
            for (int np = 0; np < 4; np++) {
                const int vr = ks * 16 + vrow_b;
                unsigned off = (unsigned)(vr * 128)
                             + (((unsigned)(np * 32) + vcolb) ^ (((unsigned)(vr & 7)) << 4));
                unsigned vf[4];
                ldsm4t(vf[0], vf[1], vf[2], vf[3], stg + 8192 + off);
                mma_f16(o[2*np],   pa, vf[0], vf[1]);
                mma_f16(o[2*np+1], pa, vf[2], vf[3]);
            }
        }
    }

    // ---- final cross-lane sum reduction ----
    float sL0 = sAcc0, sL1 = sAcc1;
    sL0 += __shfl_xor_sync(0xffffffffu, sL0, 1);
    sL0 += __shfl_xor_sync(0xffffffffu, sL0, 2);
    sL1 += __shfl_xor_sync(0xffffffffu, sL1, 1);
    sL1 += __shfl_xor_sync(0xffffffffu, sL1, 2);

    // ---- normalize + emit fp16 into g_AOh ----
    const float inv0 = 1.f / sL0, inv1 = 1.f / sL1;
    const int qr = q0 + wid * 16 + (lane >> 2);
    const size_t base0 = ((size_t)(b * SEQ + qr)) * DIM + h * HD;
    const size_t base1 = base0 + (size_t)8 * DIM;
#pragma unroll
    for (int nn = 0; nn < 8; nn++) {
        const int c = nn * 8 + (lane & 3) * 2;
        *(unsigned*)(g_AOh + base0 + c) = packh2(o[nn][0] * inv0, o[nn][1] * inv0);
        *(unsigned*)(g_AOh + base1 + c) = packh2(o[nn][2] * inv1, o[nn][3] * inv1);
    }
}

// ---------------------------------------------------------------------------
extern "C" void kernel_launch(void* const* d_in, const int* in_sizes, int n_in,
                              void* d_out, int out_size)
{
    const float* x     = (const float*)d_in[0];
    const float* mask  = (const float*)d_in[1];
    const float* bias  = (const float*)d_in[2];
    const float* Wqkv  = (const float*)d_in[3];
    const float* bqkv  = (const float*)d_in[4];
    const float* Wout  = (const float*)d_in[5];
    const float* bout  = (const float*)d_in[6];
    float* out = (float*)d_out;

    cudaFuncSetAttribute(mma_gemm_kernel<false>,
                         cudaFuncAttributeMaxDynamicSharedMemorySize, GEMM_SMEM);
    cudaFuncSetAttribute(mma_gemm_kernel<true>,
                         cudaFuncAttributeMaxDynamicSharedMemorySize, GEMM_SMEM);
    cudaFuncSetAttribute(attn_mma_kernel,
                         cudaFuncAttributeMaxDynamicSharedMemorySize, ATTN_SMEM);

    __half *x16, *w1h, *w2hi, *w2lo, *aoh;
    cudaGetSymbolAddress((void**)&x16,  g_X16);
    cudaGetSymbolAddress((void**)&w1h,  g_W1h);
    cudaGetSymbolAddress((void**)&w2hi, g_W2hi);
    cudaGetSymbolAddress((void**)&w2lo, g_W2lo);
    cudaGetSymbolAddress((void**)&aoh,  g_AOh);

    conv_x16_kernel<<<(MROWS * DIM / 4 + 255) / 256, 256>>>(x, x16,
                                                            MROWS * DIM / 4);
    conv_transpose_kernel<<<dim3(DIM / 32, QKVN / 32), dim3(32, 8)>>>(
        Wqkv, w1h, nullptr, DIM, QKVN);
    conv_transpose_kernel<<<dim3(DIM / 32, DIM / 32), dim3(32, 8)>>>(
        Wout, w2hi, w2lo, DIM, DIM);
    mb_kernel<<<(BATCH * SEQ * SEQ / 8 + 255) / 256, 256>>>(
        mask, bias, BATCH * SEQ * SEQ / 8);

    // QKV projection: plain fp16 HMMA (outputs are fp16-rounded anyway)
    mma_gemm_kernel<false><<<dim3(QKVN / 128, MROWS / 128), 256, GEMM_SMEM>>>(
        x16, w1h, nullptr, bqkv, nullptr, 1);

    attn_mma_kernel<<<dim3(SEQ / 128, BATCH * NH), 256, ATTN_SMEM>>>();

    // Output projection: keep split-fp16 weights (fp32 output precision)
    mma_gemm_kernel<true><<<dim3(DIM / 128, MROWS / 128), 256, GEMM_SMEM>>>(
        aoh, w2hi, w2lo, bout, out, 0);
}

// round 13
// speedup vs baseline: 1.4537x; 1.1188x over previous
#include <cuda_runtime.h>
#include <cuda_bf16.h>
#include <cuda_fp16.h>

#define BATCH 2
#define SEQ   2048
#define DIM   1024
#define NH    16
#define HD    64
#define MROWS (BATCH*SEQ)   // 4096
#define QKVN  (3*DIM)       // 3072
#define LOG2E 1.4426950408889634f

// ---------------- scratch (__device__ globals; no runtime allocs) ----------
__device__ __half g_Qh[(size_t)BATCH*NH*SEQ*HD];     // fp16, pre-scaled 0.125*log2e
__device__ __half g_Kh[(size_t)BATCH*NH*SEQ*HD];
__device__ __half g_Vh[(size_t)BATCH*NH*SEQ*HD];
__device__ __half g_X16[(size_t)MROWS*DIM];          // x in fp16
__device__ __half g_W1h[(size_t)QKVN*DIM];           // Wqkv^T fp16
__device__ __half g_W2h[(size_t)DIM*DIM];            // Wout^T fp16
__device__ __half g_AOh[(size_t)MROWS*DIM];          // attention out fp16
__device__ __half g_MB[(size_t)BATCH*SEQ*SEQ];       // (mask + bias)*log2e (fp16)

// ---------------- helpers ---------------------------------------------------
__device__ __forceinline__ unsigned smem_u32(const void* p) {
    unsigned a;
    asm("{ .reg .u64 t; cvta.to.shared.u64 t, %1; cvt.u32.u64 %0, t; }"
        : "=r"(a) : "l"(p));
    return a;
}
__device__ __forceinline__ void ldsm4(unsigned& r0, unsigned& r1,
                                      unsigned& r2, unsigned& r3, unsigned a) {
    asm volatile("ldmatrix.sync.aligned.m8n8.x4.shared.b16 {%0,%1,%2,%3}, [%4];"
                 : "=r"(r0), "=r"(r1), "=r"(r2), "=r"(r3) : "r"(a));
}
__device__ __forceinline__ void ldsm4t(unsigned& r0, unsigned& r1,
                                       unsigned& r2, unsigned& r3, unsigned a) {
    asm volatile("ldmatrix.sync.aligned.m8n8.x4.trans.shared.b16 {%0,%1,%2,%3}, [%4];"
                 : "=r"(r0), "=r"(r1), "=r"(r2), "=r"(r3) : "r"(a));
}
__device__ __forceinline__ void mma_f16(float* c, const unsigned* a,
                                        unsigned b0, unsigned b1) {
    asm volatile(
        "mma.sync.aligned.m16n8k16.row.col.f32.f16.f16.f32 "
        "{%0,%1,%2,%3}, {%4,%5,%6,%7}, {%8,%9}, {%0,%1,%2,%3};"
        : "+f"(c[0]), "+f"(c[1]), "+f"(c[2]), "+f"(c[3])
        : "r"(a[0]), "r"(a[1]), "r"(a[2]), "r"(a[3]), "r"(b0), "r"(b1));
}
__device__ __forceinline__ void cp16(unsigned dst, const void* src) {
    asm volatile("cp.async.cg.shared.global [%0], [%1], 16;"
                 :: "r"(dst), "l"(src) : "memory");
}
__device__ __forceinline__ void cp_commit() {
    asm volatile("cp.async.commit_group;" ::: "memory");
}
__device__ __forceinline__ unsigned packh2(float a, float b) {
    unsigned r;
    asm("cvt.rn.f16x2.f32 %0, %1, %2;" : "=r"(r) : "f"(b), "f"(a));
    return r;
}
// MUFU 2^t (fp32)
__device__ __forceinline__ float ex2f(float t) {
    float r;
    asm("ex2.approx.f32 %0, %1;" : "=f"(r) : "f"(t));
    return r;
}
// MUFU 2^t on packed half2
__device__ __forceinline__ unsigned ex2h2(unsigned t) {
    unsigned r;
    asm("ex2.approx.f16x2 %0, %1;" : "=r"(r) : "r"(t));
    return r;
}
__device__ __forceinline__ unsigned hadd2u(unsigned a, unsigned b) {
    unsigned r;
    asm("add.f16x2 %0, %1, %2;" : "=r"(r) : "r"(a), "r"(b));
    return r;
}
// swizzled offset in a [rows][32 f16] tile (64B rows)
__device__ __forceinline__ unsigned swz64(int row, unsigned colb) {
    return (unsigned)(row * 64) + (colb ^ (((unsigned)(row >> 1) & 3u) << 4));
}

#define GEMM_STAGE 16384            // A 8KB | B 8KB
#define GEMM_SMEM  (3*GEMM_STAGE)   // 48 KB

// ---------------------------------------------------------------------------
// conversions
// ---------------------------------------------------------------------------
__global__ __launch_bounds__(256) void conv_x16_kernel(
    const float* __restrict__ src, __half* __restrict__ dst, int n4)
{
    int i = blockIdx.x * 256 + threadIdx.x;
    if (i >= n4) return;
    float4 v = *((const float4*)src + i);
    uint2 o;
    o.x = packh2(v.x, v.y);
    o.y = packh2(v.z, v.w);
    ((uint2*)dst)[i] = o;
}

// transpose to fp16: W[K][N] -> T[N][K]
__global__ void conv_transpose_kernel(
    const float* __restrict__ W, __half* __restrict__ T, int K, int N)
{
    __shared__ float t[32][33];
    const int k0 = blockIdx.x * 32, n0 = blockIdx.y * 32;
    const int tx = threadIdx.x, ty = threadIdx.y;
    for (int i = ty; i < 32; i += 8)
        t[i][tx] = W[(size_t)(k0 + i) * N + n0 + tx];
    __syncthreads();
    for (int i = ty; i < 32; i += 8)
        T[(size_t)(n0 + i) * K + k0 + tx] = __float2half(t[tx][i]);
}

// combined (mask+bias)*log2e in fp16
__global__ __launch_bounds__(256) void mb_kernel(
    const float* __restrict__ mask, const float* __restrict__ bias, int n8)
{
    int i = blockIdx.x * 256 + threadIdx.x;
    if (i >= n8) return;
    const int per_b = SEQ * SEQ / 8;
    int r = i % per_b;
    float4 m0 = ((const float4*)mask)[r*2+0];
    float4 m1 = ((const float4*)mask)[r*2+1];
    float4 b0 = ((const float4*)bias)[i*2+0];
    float4 b1 = ((const float4*)bias)[i*2+1];
    __half2 o[4];
    o[0] = __floats2half2_rn((m0.x + b0.x) * LOG2E, (m0.y + b0.y) * LOG2E);
    o[1] = __floats2half2_rn((m0.z + b0.z) * LOG2E, (m0.w + b0.w) * LOG2E);
    o[2] = __floats2half2_rn((m1.x + b1.x) * LOG2E, (m1.y + b1.y) * LOG2E);
    o[3] = __floats2half2_rn((m1.z + b1.z) * LOG2E, (m1.w + b1.w) * LOG2E);
    ((uint4*)g_MB)[i] = *(uint4*)o;
}

// ---------------------------------------------------------------------------
// HMMA GEMM: A, B single fp16. BK=32, 3-stage single-sync cp.async pipeline,
// 2 CTAs/SM.
// mode 0: out fp32 + bias. mode 1: emit fp16 Q (scaled 0.125*log2e) / K / V.
// ---------------------------------------------------------------------------
__global__ __launch_bounds__(256, 2) void mma_gemm_kernel(
    const __half* __restrict__ A, const __half* __restrict__ B,
    const float* __restrict__ bias, float* __restrict__ out, int mode)
{
    extern __shared__ char smraw[];
    const unsigned sbase = smem_u32(smraw);
    const int tid  = threadIdx.x;
    const int wid  = tid >> 5;
    const int lane = tid & 31;
    const int warp_m = wid & 3;
    const int warp_n = wid >> 2;
    const int row_a = blockIdx.y * 128;
    const int col0  = blockIdx.x * 128;

    float acc[2][8][4];
#pragma unroll
    for (int i = 0; i < 2; i++)
#pragma unroll
        for (int j = 0; j < 8; j++)
#pragma unroll
            for (int c = 0; c < 4; c++) acc[i][j][c] = 0.f;

    auto issue = [&](int t) {
        const int k0 = t * 32;
        const unsigned stage = (unsigned)((t % 3) * GEMM_STAGE);
#pragma unroll
        for (int p = 0; p < 2; p++) {
            const __half* src = (p == 0) ? A : B;
            const int rb = (p == 0) ? row_a : col0;
            const unsigned pb = stage + (unsigned)p * 8192u;
#pragma unroll
            for (int i = 0; i < 2; i++) {
                const int e = tid + i * 256;
                const int r = e >> 2, c16 = e & 3;
                cp16(sbase + pb + swz64(r, (unsigned)(c16 * 16)),
                     src + (size_t)(rb + r) * DIM + k0 + c16 * 8);
            }
        }
        cp_commit();
    };

    issue(0); issue(1);

    const int amat = lane >> 3;
    const int arow_l = (lane & 7) + ((amat & 1) << 3);
    const unsigned acolx = (unsigned)((amat >> 1) << 4);
    const int brow_l = (lane & 7) + ((amat >> 1) << 3);
    const unsigned bcolx = (unsigned)((amat & 1) << 4);

    for (int t = 0; t < 32; t++) {
        if (t < 31) asm volatile("cp.async.wait_group 1;" ::: "memory");
        else        asm volatile("cp.async.wait_group 0;" ::: "memory");
        __syncthreads();
        if (t + 2 < 32) issue(t + 2);

        const unsigned stage = sbase + (unsigned)((t % 3) * GEMM_STAGE);
#pragma unroll
        for (int ks = 0; ks < 2; ks++) {
            const unsigned kb = (unsigned)(ks * 32);
            unsigned bh[4][4];
#pragma unroll
            for (int np = 0; np < 4; np++) {
                const int r = warp_n * 64 + np * 16 + brow_l;
                const unsigned ro = swz64(r, kb + bcolx);
                ldsm4(bh[np][0], bh[np][1], bh[np][2], bh[np][3], stage + 8192 + ro);
            }
#pragma unroll
            for (int mf = 0; mf < 2; mf++) {
                const int r = warp_m * 32 + mf * 16 + arow_l;
                const unsigned ro = swz64(r, kb + acolx);
                unsigned af[4];
                ldsm4(af[0], af[1], af[2], af[3], stage + ro);
#pragma unroll
                for (int nn = 0; nn < 8; nn++) {
                    const int np = nn >> 1, hf = (nn & 1) * 2;
                    mma_f16(acc[mf][nn], af, bh[np][hf], bh[np][hf + 1]);
                }
            }
        }
    }

#pragma unroll
    for (int mf = 0; mf < 2; mf++) {
#pragma unroll
        for (int nn = 0; nn < 8; nn++) {
            const int gc = col0 + warp_n * 64 + nn * 8 + (lane & 3) * 2;
            const int r0 = row_a + warp_m * 32 + mf * 16 + (lane >> 2);
            const float bx = bias[gc], by = bias[gc + 1];
            float2 v0, v1;
            v0.x = acc[mf][nn][0] + bx; v0.y = acc[mf][nn][1] + by;
            v1.x = acc[mf][nn][2] + bx; v1.y = acc[mf][nn][3] + by;
            if (mode == 0) {
                *(float2*)(out + (size_t)r0 * DIM + gc)       = v0;
                *(float2*)(out + (size_t)(r0 + 8) * DIM + gc) = v1;
            } else {
                const int sel = gc >> 10;
                const int w   = gc & 1023;
                const int h   = w >> 6;
                const int d0  = w & 63;
                __half* dst;
                float sc;
                if (sel == 0)      { dst = g_Qh; sc = 0.125f * LOG2E; }
                else if (sel == 1) { dst = g_Kh; sc = 1.f; }
                else               { dst = g_Vh; sc = 1.f; }
                const int b0 = r0 >> 11, s0 = r0 & 2047;
                const int r1 = r0 + 8;
                const int b1 = r1 >> 11, s1 = r1 & 2047;
                const size_t i0 = (((size_t)b0 * NH + h) * SEQ + s0) * HD + d0;
                const size_t i1 = (((size_t)b1 * NH + h) * SEQ + s1) * HD + d0;
                *(unsigned*)(dst + i0) = packh2(v0.x * sc, v0.y * sc);
                *(unsigned*)(dst + i1) = packh2(v1.x * sc, v1.y * sc);
            }
        }
    }
}

// ---------------------------------------------------------------------------
// fp16 flash attention (log2-domain, f16x2 MUFU exp2). 128 q x 64 k tiles,
// 8 warps, 2 CTAs/SM, 3-stage single-sync pipeline. Mask+bias streamed
// through the cp.async pipeline; Q fragments hoisted to registers.
// Stage layout: K 8KB | V 8KB | MB 16KB = 32KB.
// ---------------------------------------------------------------------------
#define ATTN_STAGE 32768
#define ATTN_SMEM  (16384 + 3*ATTN_STAGE)   // 112 KB -> 2 CTAs = 224 KB/SM

__global__ __launch_bounds__(256, 2) void attn_mma_kernel()
{
    extern __shared__ char smraw[];
    const unsigned sbase = smem_u32(smraw);
    const int tid = threadIdx.x, wid = tid >> 5, lane = tid & 31;
    const int bh = blockIdx.y, b = bh >> 4, h = bh & 15;
    const int q0 = blockIdx.x * 128;

    const __half* Qg = g_Qh + (size_t)bh * SEQ * HD;
    const __half* Kg = g_Kh + (size_t)bh * SEQ * HD;
    const __half* Vg = g_Vh + (size_t)bh * SEQ * HD;
    const __half* MBg = g_MB + (size_t)(b * SEQ + q0) * SEQ;

    // Q tile -> smem (128B rows, 128B swizzle), own commit group
#pragma unroll
    for (int i = 0; i < 4; i++) {
        const int e = tid + i * 256;
        const int r = e >> 3, c4 = e & 7;
        unsigned off = (unsigned)(r * 128 + c4 * 16);
        off ^= (off >> 3) & 0x70;
        cp16(sbase + off, Qg + (size_t)(q0 + r) * HD + c4 * 8);
    }
    cp_commit();

    auto issue = [&](int t) {
        const int k0 = t * 64;
        const unsigned stg = 16384u + (unsigned)((t % 3) * ATTN_STAGE);
#pragma unroll
        for (int p = 0; p < 2; p++) {
            const __half* src = p ? Vg : Kg;
#pragma unroll
            for (int i = 0; i < 2; i++) {
                const int e = tid + i * 256;
                const int r = e >> 3, c4 = e & 7;
                unsigned off = (unsigned)(r * 128 + c4 * 16);
                off ^= (off >> 3) & 0x70;
                cp16(sbase + stg + (unsigned)p * 8192u + off,
                     src + (size_t)(k0 + r) * HD + c4 * 8);
            }
        }
#pragma unroll
        for (int i = 0; i < 4; i++) {
            const int e = tid + i * 256;
            const int r = e >> 3, c4 = e & 7;
            unsigned off = (unsigned)(r * 128 + c4 * 16);
            off ^= (off >> 3) & 0x70;
            cp16(sbase + stg + 16384u + off,
                 MBg + (size_t)r * SEQ + k0 + c4 * 8);
        }
        cp_commit();
    };
    issue(0); issue(1);

    const int amat = lane >> 3;
    const int arow = wid * 16 + (lane & 7) + ((amat & 1) << 3);
    const unsigned acolx = (unsigned)((amat >> 1) << 4);
    const int krow_b = (lane & 7) + ((amat >> 1) << 3);
    const unsigned kcolx = (unsigned)((amat & 1) << 4);
    const int vrow_b = (lane & 7) + ((amat & 1) << 3);
    const unsigned vcolb = (unsigned)((lane >> 4) << 4);

    const int qr0 = wid * 16 + (lane >> 2);
    const unsigned mb_l = (unsigned)((lane & 3) * 4);

    float o[8][4];
#pragma unroll
    for (int nn = 0; nn < 8; nn++)
#pragma unroll
        for (int c = 0; c < 4; c++) o[nn][c] = 0.f;
    float sM0 = -1e30f, sM1 = -1e30f, sAcc0 = 0.f, sAcc1 = 0.f;

    unsigned qf[4][4];   // Q fragments, loaded once

    for (int t = 0; t < 32; t++) {
        if (t < 31) asm volatile("cp.async.wait_group 1;" ::: "memory");
        else        asm volatile("cp.async.wait_group 0;" ::: "memory");
        __syncthreads();
        if (t + 2 < 32) issue(t + 2);

        const unsigned stg = sbase + 16384u + (unsigned)((t % 3) * ATTN_STAGE);

        if (t == 0) {
#pragma unroll
            for (int ks = 0; ks < 4; ks++) {
                unsigned qoff = (unsigned)(arow * 128)
                              + (((unsigned)(ks * 32) + acolx) ^ (((unsigned)(arow & 7)) << 4));
                ldsm4(qf[ks][0], qf[ks][1], qf[ks][2], qf[ks][3], sbase + qoff);
            }
        }

        // ---- S = Q.K^T (fp16, log2-domain) ----
        float s[8][4];
#pragma unroll
        for (int nn = 0; nn < 8; nn++)
#pragma unroll
            for (int c = 0; c < 4; c++) s[nn][c] = 0.f;
#pragma unroll
        for (int ks = 0; ks < 4; ks++) {
#pragma unroll
            for (int np = 0; np < 4; np++) {
                const int kr = np * 16 + krow_b;
                unsigned off = (unsigned)(kr * 128)
                             + (((unsigned)(ks * 32) + kcolx) ^ (((unsigned)(kr & 7)) << 4));
                unsigned kf[4];
                ldsm4(kf[0], kf[1], kf[2], kf[3], stg + off);
                mma_f16(s[2*np],   qf[ks], kf[0], kf[1]);
                mma_f16(s[2*np+1], qf[ks], kf[2], kf[3]);
            }
        }

        // ---- + (mask+bias)*log2e from smem MB tile (fp32 adds) ----
        const unsigned mb0 = stg + 16384u + (unsigned)(qr0 * 128) + mb_l;
        const unsigned mb1 = mb0 + 8u * 128u;
        const unsigned sw0 = ((unsigned)(qr0 & 7)) << 4;
        const unsigned sw1 = ((unsigned)((qr0 + 8) & 7)) << 4;
#pragma unroll
        for (int nn = 0; nn < 8; nn++) {
            const unsigned u = (unsigned)(nn * 16);
            __half2 h0 = *(__half2*)(smraw + (mb0 + (u ^ sw0)) - sbase);
            __half2 h1 = *(__half2*)(smraw + (mb1 + (u ^ sw1)) - sbase);
            float2 f0 = __half22float2(h0);
            float2 f1 = __half22float2(h1);
            s[nn][0] += f0.x; s[nn][1] += f0.y;
            s[nn][2] += f1.x; s[nn][3] += f1.y;
        }

        // ---- online softmax: fp32 max, f16x2 exp2 ----
        float mx0 = -1e30f, mx1 = -1e30f;
#pragma unroll
        for (int nn = 0; nn < 8; nn++) {
            mx0 = fmaxf(mx0, fmaxf(s[nn][0], s[nn][1]));
            mx1 = fmaxf(mx1, fmaxf(s[nn][2], s[nn][3]));
        }
        mx0 = fmaxf(mx0, __shfl_xor_sync(0xffffffffu, mx0, 1));
        mx0 = fmaxf(mx0, __shfl_xor_sync(0xffffffffu, mx0, 2));
        mx1 = fmaxf(mx1, __shfl_xor_sync(0xffffffffu, mx1, 1));
        mx1 = fmaxf(mx1, __shfl_xor_sync(0xffffffffu, mx1, 2));
        const float old0 = sM0, old1 = sM1;
        const float mn0 = fmaxf(sM0, mx0), mn1 = fmaxf(sM1, mx1);
        sM0 = mn0; sM1 = mn1;

        // p = 2^(s-m), packed half2 per (row, col pair); P feeds PV directly
        unsigned p0[8], p1[8];
#pragma unroll
        for (int nn = 0; nn < 8; nn++) {
            p0[nn] = ex2h2(packh2(s[nn][0] - mn0, s[nn][1] - mn0));
            p1[nn] = ex2h2(packh2(s[nn][2] - mn1, s[nn][3] - mn1));
        }

        // tile sums via HADD2 tree (fp16), finalized in fp32
        unsigned t0 = hadd2u(hadd2u(hadd2u(p0[0], p0[1]), hadd2u(p0[2], p0[3])),
                             hadd2u(hadd2u(p0[4], p0[5]), hadd2u(p0[6], p0[7])));
        unsigned t1 = hadd2u(hadd2u(hadd2u(p1[0], p1[1]), hadd2u(p1[2], p1[3])),
                             hadd2u(hadd2u(p1[4], p1[5]), hadd2u(p1[6], p1[7])));
        __half2 ht0 = *(__half2*)&t0;
        __half2 ht1 = *(__half2*)&t1;
        float ls0 = __low2float(ht0) + __high2float(ht0);
        float ls1 = __low2float(ht1) + __high2float(ht1);

        const bool changed = (mn0 != old0) || (mn1 != old1);
        if (__any_sync(0xffffffffu, changed)) {
            const float c0 = ex2f(old0 - mn0);
            const float c1 = ex2f(old1 - mn1);
            sAcc0 = sAcc0 * c0 + ls0;
            sAcc1 = sAcc1 * c1 + ls1;
#pragma unroll
            for (int nn = 0; nn < 8; nn++) {
                o[nn][0] *= c0; o[nn][1] *= c0;
                o[nn][2] *= c1; o[nn][3] *= c1;
            }
        } else {
            sAcc0 += ls0;
            sAcc1 += ls1;
        }

        // ---- O += P.V (fp16) ----
#pragma unroll
        for (int ks = 0; ks < 4; ks++) {
            unsigned pa[4];
            pa[0] = p0[2*ks];
            pa[1] = p1[2*ks];
            pa[2] = p0[2*ks+1];
            pa[3] = p1[2*ks+1];
#pragma unroll
            for (int np = 0; np < 4; np++) {
                const int vr = ks * 16 + vrow_b;
                unsigned off = (unsigned)(vr * 128)
                             + (((unsigned)(np * 32) + vcolb) ^ (((unsigned)(vr & 7)) << 4));
                unsigned vf[4];
                ldsm4t(vf[0], vf[1], vf[2], vf[3], stg + 8192 + off);
                mma_f16(o[2*np],   pa, vf[0], vf[1]);
                mma_f16(o[2*np+1], pa, vf[2], vf[3]);
            }
        }
    }

    // ---- final cross-lane sum reduction ----
    float sL0 = sAcc0, sL1 = sAcc1;
    sL0 += __shfl_xor_sync(0xffffffffu, sL0, 1);
    sL0 += __shfl_xor_sync(0xffffffffu, sL0, 2);
    sL1 += __shfl_xor_sync(0xffffffffu, sL1, 1);
    sL1 += __shfl_xor_sync(0xffffffffu, sL1, 2);

    // ---- normalize + emit fp16 into g_AOh ----
    const float inv0 = 1.f / sL0, inv1 = 1.f / sL1;
    const int qr = q0 + wid * 16 + (lane >> 2);
    const size_t base0 = ((size_t)(b * SEQ + qr)) * DIM + h * HD;
    const size_t base1 = base0 + (size_t)8 * DIM;
#pragma unroll
    for (int nn = 0; nn < 8; nn++) {
        const int c = nn * 8 + (lane & 3) * 2;
        *(unsigned*)(g_AOh + base0 + c) = packh2(o[nn][0] * inv0, o[nn][1] * inv0);
        *(unsigned*)(g_AOh + base1 + c) = packh2(o[nn][2] * inv1, o[nn][3] * inv1);
    }
}

// ---------------------------------------------------------------------------
extern "C" void kernel_launch(void* const* d_in, const int* in_sizes, int n_in,
                              void* d_out, int out_size)
{
    const float* x     = (const float*)d_in[0];
    const float* mask  = (const float*)d_in[1];
    const float* bias  = (const float*)d_in[2];
    const float* Wqkv  = (const float*)d_in[3];
    const float* bqkv  = (const float*)d_in[4];
    const float* Wout  = (const float*)d_in[5];
    const float* bout  = (const float*)d_in[6];
    float* out = (float*)d_out;

    cudaFuncSetAttribute(mma_gemm_kernel,
                         cudaFuncAttributeMaxDynamicSharedMemorySize, GEMM_SMEM);
    cudaFuncSetAttribute(attn_mma_kernel,
                         cudaFuncAttributeMaxDynamicSharedMemorySize, ATTN_SMEM);

    __half *x16, *w1h, *w2h, *aoh;
    cudaGetSymbolAddress((void**)&x16, g_X16);
    cudaGetSymbolAddress((void**)&w1h, g_W1h);
    cudaGetSymbolAddress((void**)&w2h, g_W2h);
    cudaGetSymbolAddress((void**)&aoh, g_AOh);

    conv_x16_kernel<<<(MROWS * DIM / 4 + 255) / 256, 256>>>(x, x16,
                                                            MROWS * DIM / 4);
    conv_transpose_kernel<<<dim3(DIM / 32, QKVN / 32), dim3(32, 8)>>>(
        Wqkv, w1h, DIM, QKVN);
    conv_transpose_kernel<<<dim3(DIM / 32, DIM / 32), dim3(32, 8)>>>(
        Wout, w2h, DIM, DIM);
    mb_kernel<<<(BATCH * SEQ * SEQ / 8 + 255) / 256, 256>>>(
        mask, bias, BATCH * SEQ * SEQ / 8);

    mma_gemm_kernel<<<dim3(QKVN / 128, MROWS / 128), 256, GEMM_SMEM>>>(
        x16, w1h, bqkv, nullptr, 1);

    attn_mma_kernel<<<dim3(SEQ / 128, BATCH * NH), 256, ATTN_SMEM>>>();

    mma_gemm_kernel<<<dim3(DIM / 128, MROWS / 128), 256, GEMM_SMEM>>>(
        aoh, w2h, bout, out, 0);
}

// round 14
// speedup vs baseline: 1.4568x; 1.0021x over previous
#include <cuda_runtime.h>
#include <cuda_bf16.h>
#include <cuda_fp16.h>

#define BATCH 2
#define SEQ   2048
#define DIM   1024
#define NH    16
#define HD    64
#define MROWS (BATCH*SEQ)   // 4096
#define QKVN  (3*DIM)       // 3072
#define LOG2E 1.4426950408889634f

// ---------------- scratch (__device__ globals; no runtime allocs) ----------
__device__ __half g_Qh[(size_t)BATCH*NH*SEQ*HD];     // fp16, pre-scaled 0.125*log2e
__device__ __half g_Kh[(size_t)BATCH*NH*SEQ*HD];
__device__ __half g_Vh[(size_t)BATCH*NH*SEQ*HD];
__device__ __half g_X16[(size_t)MROWS*DIM];          // x in fp16
__device__ __half g_W1h[(size_t)QKVN*DIM];           // Wqkv^T fp16
__device__ __half g_W2h[(size_t)DIM*DIM];            // Wout^T fp16
__device__ __half g_AOh[(size_t)MROWS*DIM];          // attention out fp16
__device__ __half g_MB[(size_t)BATCH*SEQ*SEQ];       // (mask + bias)*log2e (fp16)

// ---------------- helpers ---------------------------------------------------
__device__ __forceinline__ unsigned smem_u32(const void* p) {
    unsigned a;
    asm("{ .reg .u64 t; cvta.to.shared.u64 t, %1; cvt.u32.u64 %0, t; }"
        : "=r"(a) : "l"(p));
    return a;
}
__device__ __forceinline__ void ldsm4(unsigned& r0, unsigned& r1,
                                      unsigned& r2, unsigned& r3, unsigned a) {
    asm volatile("ldmatrix.sync.aligned.m8n8.x4.shared.b16 {%0,%1,%2,%3}, [%4];"
                 : "=r"(r0), "=r"(r1), "=r"(r2), "=r"(r3) : "r"(a));
}
__device__ __forceinline__ void ldsm4t(unsigned& r0, unsigned& r1,
                                       unsigned& r2, unsigned& r3, unsigned a) {
    asm volatile("ldmatrix.sync.aligned.m8n8.x4.trans.shared.b16 {%0,%1,%2,%3}, [%4];"
                 : "=r"(r0), "=r"(r1), "=r"(r2), "=r"(r3) : "r"(a));
}
__device__ __forceinline__ void mma_f16(float* c, const unsigned* a,
                                        unsigned b0, unsigned b1) {
    asm volatile(
        "mma.sync.aligned.m16n8k16.row.col.f32.f16.f16.f32 "
        "{%0,%1,%2,%3}, {%4,%5,%6,%7}, {%8,%9}, {%0,%1,%2,%3};"
        : "+f"(c[0]), "+f"(c[1]), "+f"(c[2]), "+f"(c[3])
        : "r"(a[0]), "r"(a[1]), "r"(a[2]), "r"(a[3]), "r"(b0), "r"(b1));
}
__device__ __forceinline__ void cp16(unsigned dst, const void* src) {
    asm volatile("cp.async.cg.shared.global [%0], [%1], 16;"
                 :: "r"(dst), "l"(src) : "memory");
}
__device__ __forceinline__ void cp_commit() {
    asm volatile("cp.async.commit_group;" ::: "memory");
}
__device__ __forceinline__ unsigned packh2(float a, float b) {
    unsigned r;
    asm("cvt.rn.f16x2.f32 %0, %1, %2;" : "=r"(r) : "f"(b), "f"(a));
    return r;
}
// MUFU 2^t (fp32)
__device__ __forceinline__ float ex2f(float t) {
    float r;
    asm("ex2.approx.f32 %0, %1;" : "=f"(r) : "f"(t));
    return r;
}
// MUFU 2^t on packed half2
__device__ __forceinline__ unsigned ex2h2(unsigned t) {
    unsigned r;
    asm("ex2.approx.f16x2 %0, %1;" : "=r"(r) : "r"(t));
    return r;
}
__device__ __forceinline__ unsigned hadd2u(unsigned a, unsigned b) {
    unsigned r;
    asm("add.f16x2 %0, %1, %2;" : "=r"(r) : "r"(a), "r"(b));
    return r;
}
// swizzled offset in a [rows][32 f16] tile (64B rows)
__device__ __forceinline__ unsigned swz64(int row, unsigned colb) {
    return (unsigned)(row * 64) + (colb ^ (((unsigned)(row >> 1) & 3u) << 4));
}

#define GEMM_STAGE 16384            // A 8KB | B 8KB
#define GEMM_SMEM  (3*GEMM_STAGE)   // 48 KB

// ---------------------------------------------------------------------------
// conversions
// ---------------------------------------------------------------------------
__global__ __launch_bounds__(256) void conv_x16_kernel(
    const float* __restrict__ src, __half* __restrict__ dst, int n4)
{
    int i = blockIdx.x * 256 + threadIdx.x;
    if (i >= n4) return;
    float4 v = *((const float4*)src + i);
    uint2 o;
    o.x = packh2(v.x, v.y);
    o.y = packh2(v.z, v.w);
    ((uint2*)dst)[i] = o;
}

// transpose to fp16: W[K][N] -> T[N][K]
__global__ void conv_transpose_kernel(
    const float* __restrict__ W, __half* __restrict__ T, int K, int N)
{
    __shared__ float t[32][33];
    const int k0 = blockIdx.x * 32, n0 = blockIdx.y * 32;
    const int tx = threadIdx.x, ty = threadIdx.y;
    for (int i = ty; i < 32; i += 8)
        t[i][tx] = W[(size_t)(k0 + i) * N + n0 + tx];
    __syncthreads();
    for (int i = ty; i < 32; i += 8)
        T[(size_t)(n0 + i) * K + k0 + tx] = __float2half(t[tx][i]);
}

// combined (mask+bias)*log2e in fp16
__global__ __launch_bounds__(256) void mb_kernel(
    const float* __restrict__ mask, const float* __restrict__ bias, int n8)
{
    int i = blockIdx.x * 256 + threadIdx.x;
    if (i >= n8) return;
    const int per_b = SEQ * SEQ / 8;
    int r = i % per_b;
    float4 m0 = ((const float4*)mask)[r*2+0];
    float4 m1 = ((const float4*)mask)[r*2+1];
    float4 b0 = ((const float4*)bias)[i*2+0];
    float4 b1 = ((const float4*)bias)[i*2+1];
    __half2 o[4];
    o[0] = __floats2half2_rn((m0.x + b0.x) * LOG2E, (m0.y + b0.y) * LOG2E);
    o[1] = __floats2half2_rn((m0.z + b0.z) * LOG2E, (m0.w + b0.w) * LOG2E);
    o[2] = __floats2half2_rn((m1.x + b1.x) * LOG2E, (m1.y + b1.y) * LOG2E);
    o[3] = __floats2half2_rn((m1.z + b1.z) * LOG2E, (m1.w + b1.w) * LOG2E);
    ((uint4*)g_MB)[i] = *(uint4*)o;
}

// ---------------------------------------------------------------------------
// HMMA GEMM: A, B single fp16. BK=32, 3-stage single-sync cp.async pipeline,
// 2 CTAs/SM.
// mode 0: out fp32 + bias. mode 1: emit fp16 Q (scaled 0.125*log2e) / K / V.
// ---------------------------------------------------------------------------
__global__ __launch_bounds__(256, 2) void mma_gemm_kernel(
    const __half* __restrict__ A, const __half* __restrict__ B,
    const float* __restrict__ bias, float* __restrict__ out, int mode)
{
    extern __shared__ char smraw[];
    const unsigned sbase = smem_u32(smraw);
    const int tid  = threadIdx.x;
    const int wid  = tid >> 5;
    const int lane = tid & 31;
    const int warp_m = wid & 3;
    const int warp_n = wid >> 2;
    const int row_a = blockIdx.y * 128;
    const int col0  = blockIdx.x * 128;

    float acc[2][8][4];
#pragma unroll
    for (int i = 0; i < 2; i++)
#pragma unroll
        for (int j = 0; j < 8; j++)
#pragma unroll
            for (int c = 0; c < 4; c++) acc[i][j][c] = 0.f;

    auto issue = [&](int t) {
        const int k0 = t * 32;
        const unsigned stage = (unsigned)((t % 3) * GEMM_STAGE);
#pragma unroll
        for (int p = 0; p < 2; p++) {
            const __half* src = (p == 0) ? A : B;
            const int rb = (p == 0) ? row_a : col0;
            const unsigned pb = stage + (unsigned)p * 8192u;
#pragma unroll
            for (int i = 0; i < 2; i++) {
                const int e = tid + i * 256;
                const int r = e >> 2, c16 = e & 3;
                cp16(sbase + pb + swz64(r, (unsigned)(c16 * 16)),
                     src + (size_t)(rb + r) * DIM + k0 + c16 * 8);
            }
        }
        cp_commit();
    };

    issue(0); issue(1);

    const int amat = lane >> 3;
    const int arow_l = (lane & 7) + ((amat & 1) << 3);
    const unsigned acolx = (unsigned)((amat >> 1) << 4);
    const int brow_l = (lane & 7) + ((amat >> 1) << 3);
    const unsigned bcolx = (unsigned)((amat & 1) << 4);

    for (int t = 0; t < 32; t++) {
        if (t < 31) asm volatile("cp.async.wait_group 1;" ::: "memory");
        else        asm volatile("cp.async.wait_group 0;" ::: "memory");
        __syncthreads();
        if (t + 2 < 32) issue(t + 2);

        const unsigned stage = sbase + (unsigned)((t % 3) * GEMM_STAGE);
#pragma unroll
        for (int ks = 0; ks < 2; ks++) {
            const unsigned kb = (unsigned)(ks * 32);
            unsigned bh[4][4];
#pragma unroll
            for (int np = 0; np < 4; np++) {
                const int r = warp_n * 64 + np * 16 + brow_l;
                const unsigned ro = swz64(r, kb + bcolx);
                ldsm4(bh[np][0], bh[np][1], bh[np][2], bh[np][3], stage + 8192 + ro);
            }
#pragma unroll
            for (int mf = 0; mf < 2; mf++) {
                const int r = warp_m * 32 + mf * 16 + arow_l;
                const unsigned ro = swz64(r, kb + acolx);
                unsigned af[4];
                ldsm4(af[0], af[1], af[2], af[3], stage + ro);
#pragma unroll
                for (int nn = 0; nn < 8; nn++) {
                    const int np = nn >> 1, hf = (nn & 1) * 2;
                    mma_f16(acc[mf][nn], af, bh[np][hf], bh[np][hf + 1]);
                }
            }
        }
    }

#pragma unroll
    for (int mf = 0; mf < 2; mf++) {
#pragma unroll
        for (int nn = 0; nn < 8; nn++) {
            const int gc = col0 + warp_n * 64 + nn * 8 + (lane & 3) * 2;
            const int r0 = row_a + warp_m * 32 + mf * 16 + (lane >> 2);
            const float bx = bias[gc], by = bias[gc + 1];
            float2 v0, v1;
            v0.x = acc[mf][nn][0] + bx; v0.y = acc[mf][nn][1] + by;
            v1.x = acc[mf][nn][2] + bx; v1.y = acc[mf][nn][3] + by;
            if (mode == 0) {
                *(float2*)(out + (size_t)r0 * DIM + gc)       = v0;
                *(float2*)(out + (size_t)(r0 + 8) * DIM + gc) = v1;
            } else {
                const int sel = gc >> 10;
                const int w   = gc & 1023;
                const int h   = w >> 6;
                const int d0  = w & 63;
                __half* dst;
                float sc;
                if (sel == 0)      { dst = g_Qh; sc = 0.125f * LOG2E; }
                else if (sel == 1) { dst = g_Kh; sc = 1.f; }
                else               { dst = g_Vh; sc = 1.f; }
                const int b0 = r0 >> 11, s0 = r0 & 2047;
                const int r1 = r0 + 8;
                const int b1 = r1 >> 11, s1 = r1 & 2047;
                const size_t i0 = (((size_t)b0 * NH + h) * SEQ + s0) * HD + d0;
                const size_t i1 = (((size_t)b1 * NH + h) * SEQ + s1) * HD + d0;
                *(unsigned*)(dst + i0) = packh2(v0.x * sc, v0.y * sc);
                *(unsigned*)(dst + i1) = packh2(v1.x * sc, v1.y * sc);
            }
        }
    }
}

// ---------------------------------------------------------------------------
// fp16 flash attention (log2-domain, f16x2 MUFU exp2). 128 q x 64 k tiles,
// 8 warps, 2 CTAs/SM, 3-stage single-sync pipeline. Mask+bias streamed
// through the cp.async pipeline; Q fragments hoisted to registers.
// Stage layout: K 8KB | V 8KB | MB 16KB = 32KB.
// ---------------------------------------------------------------------------
#define ATTN_STAGE 32768
#define ATTN_SMEM  (16384 + 3*ATTN_STAGE)   // 112 KB -> 2 CTAs = 224 KB/SM

__global__ __launch_bounds__(256, 2) void attn_mma_kernel()
{
    extern __shared__ char smraw[];
    const unsigned sbase = smem_u32(smraw);
    const int tid = threadIdx.x, wid = tid >> 5, lane = tid & 31;
    const int bh = blockIdx.y, b = bh >> 4, h = bh & 15;
    const int q0 = blockIdx.x * 128;

    const __half* Qg = g_Qh + (size_t)bh * SEQ * HD;
    const __half* Kg = g_Kh + (size_t)bh * SEQ * HD;
    const __half* Vg = g_Vh + (size_t)bh * SEQ * HD;
    const __half* MBg = g_MB + (size_t)(b * SEQ + q0) * SEQ;

    // Q tile -> smem (128B rows, 128B swizzle), own commit group
#pragma unroll
    for (int i = 0; i < 4; i++) {
        const int e = tid + i * 256;
        const int r = e >> 3, c4 = e & 7;
        unsigned off = (unsigned)(r * 128 + c4 * 16);
        off ^= (off >> 3) & 0x70;
        cp16(sbase + off, Qg + (size_t)(q0 + r) * HD + c4 * 8);
    }
    cp_commit();

    auto issue = [&](int t) {
        const int k0 = t * 64;
        const unsigned stg = 16384u + (unsigned)((t % 3) * ATTN_STAGE);
#pragma unroll
        for (int p = 0; p < 2; p++) {
            const __half* src = p ? Vg : Kg;
#pragma unroll
            for (int i = 0; i < 2; i++) {
                const int e = tid + i * 256;
                const int r = e >> 3, c4 = e & 7;
                unsigned off = (unsigned)(r * 128 + c4 * 16);
                off ^= (off >> 3) & 0x70;
                cp16(sbase + stg + (unsigned)p * 8192u + off,
                     src + (size_t)(k0 + r) * HD + c4 * 8);
            }
        }
#pragma unroll
        for (int i = 0; i < 4; i++) {
            const int e = tid + i * 256;
            const int r = e >> 3, c4 = e & 7;
            unsigned off = (unsigned)(r * 128 + c4 * 16);
            off ^= (off >> 3) & 0x70;
            cp16(sbase + stg + 16384u + off,
                 MBg + (size_t)r * SEQ + k0 + c4 * 8);
        }
        cp_commit();
    };
    issue(0); issue(1);

    const int amat = lane >> 3;
    const int arow = wid * 16 + (lane & 7) + ((amat & 1) << 3);
    const unsigned acolx = (unsigned)((amat >> 1) << 4);
    const int krow_b = (lane & 7) + ((amat >> 1) << 3);
    const unsigned kcolx = (unsigned)((amat & 1) << 4);
    const int vrow_b = (lane & 7) + ((amat & 1) << 3);
    const unsigned vcolb = (unsigned)((lane >> 4) << 4);

    const int qr0 = wid * 16 + (lane >> 2);
    const unsigned mb_l = (unsigned)((lane & 3) * 4);

    float o[8][4];
#pragma unroll
    for (int nn = 0; nn < 8; nn++)
#pragma unroll
        for (int c = 0; c < 4; c++) o[nn][c] = 0.f;
    float sM0 = -1e30f, sM1 = -1e30f, sAcc0 = 0.f, sAcc1 = 0.f;

    unsigned qf[4][4];   // Q fragments, loaded once

    for (int t = 0; t < 32; t++) {
        if (t < 31) asm volatile("cp.async.wait_group 1;" ::: "memory");
        else        asm volatile("cp.async.wait_group 0;" ::: "memory");
        __syncthreads();
        if (t + 2 < 32) issue(t + 2);

        const unsigned stg = sbase + 16384u + (unsigned)((t % 3) * ATTN_STAGE);

        if (t == 0) {
#pragma unroll
            for (int ks = 0; ks < 4; ks++) {
                unsigned qoff = (unsigned)(arow * 128)
                              + (((unsigned)(ks * 32) + acolx) ^ (((unsigned)(arow & 7)) << 4));
                ldsm4(qf[ks][0], qf[ks][1], qf[ks][2], qf[ks][3], sbase + qoff);
            }
        }

        // ---- S = Q.K^T (fp16, log2-domain) ----
        float s[8][4];
#pragma unroll
        for (int nn = 0; nn < 8; nn++)
#pragma unroll
            for (int c = 0; c < 4; c++) s[nn][c] = 0.f;
#pragma unroll
        for (int ks = 0; ks < 4; ks++) {
#pragma unroll
            for (int np = 0; np < 4; np++) {
                const int kr = np * 16 + krow_b;
                unsigned off = (unsigned)(kr * 128)
                             + (((unsigned)(ks * 32) + kcolx) ^ (((unsigned)(kr & 7)) << 4));
                unsigned kf[4];
                ldsm4(kf[0], kf[1], kf[2], kf[3], stg + off);
                mma_f16(s[2*np],   qf[ks], kf[0], kf[1]);
                mma_f16(s[2*np+1], qf[ks], kf[2], kf[3]);
            }
        }

        // ---- + (mask+bias)*log2e from smem MB tile (fp32 adds) ----
        const unsigned mb0 = stg + 16384u + (unsigned)(qr0 * 128) + mb_l;
        const unsigned mb1 = mb0 + 8u * 128u;
        const unsigned sw0 = ((unsigned)(qr0 & 7)) << 4;
        const unsigned sw1 = ((unsigned)((qr0 + 8) & 7)) << 4;
#pragma unroll
        for (int nn = 0; nn < 8; nn++) {
            const unsigned u = (unsigned)(nn * 16);
            __half2 h0 = *(__half2*)(smraw + (mb0 + (u ^ sw0)) - sbase);
            __half2 h1 = *(__half2*)(smraw + (mb1 + (u ^ sw1)) - sbase);
            float2 f0 = __half22float2(h0);
            float2 f1 = __half22float2(h1);
            s[nn][0] += f0.x; s[nn][1] += f0.y;
            s[nn][2] += f1.x; s[nn][3] += f1.y;
        }

        // ---- online softmax: fp32 max, f16x2 exp2 ----
        float mx0 = -1e30f, mx1 = -1e30f;
#pragma unroll
        for (int nn = 0; nn < 8; nn++) {
            mx0 = fmaxf(mx0, fmaxf(s[nn][0], s[nn][1]));
            mx1 = fmaxf(mx1, fmaxf(s[nn][2], s[nn][3]));
        }
        mx0 = fmaxf(mx0, __shfl_xor_sync(0xffffffffu, mx0, 1));
        mx0 = fmaxf(mx0, __shfl_xor_sync(0xffffffffu, mx0, 2));
        mx1 = fmaxf(mx1, __shfl_xor_sync(0xffffffffu, mx1, 1));
        mx1 = fmaxf(mx1, __shfl_xor_sync(0xffffffffu, mx1, 2));
        const float old0 = sM0, old1 = sM1;
        const float mn0 = fmaxf(sM0, mx0), mn1 = fmaxf(sM1, mx1);
        sM0 = mn0; sM1 = mn1;

        // p = 2^(s-m), packed half2 per (row, col pair); P feeds PV directly
        unsigned p0[8], p1[8];
#pragma unroll
        for (int nn = 0; nn < 8; nn++) {
            p0[nn] = ex2h2(packh2(s[nn][0] - mn0, s[nn][1] - mn0));
            p1[nn] = ex2h2(packh2(s[nn][2] - mn1, s[nn][3] - mn1));
        }

        // tile sums via HADD2 tree (fp16), finalized in fp32
        unsigned t0 = hadd2u(hadd2u(hadd2u(p0[0], p0[1]), hadd2u(p0[2], p0[3])),
                             hadd2u(hadd2u(p0[4], p0[5]), hadd2u(p0[6], p0[7])));
        unsigned t1 = hadd2u(hadd2u(hadd2u(p1[0], p1[1]), hadd2u(p1[2], p1[3])),
                             hadd2u(hadd2u(p1[4], p1[5]), hadd2u(p1[6], p1[7])));
        __half2 ht0 = *(__half2*)&t0;
        __half2 ht1 = *(__half2*)&t1;
        float ls0 = __low2float(ht0) + __high2float(ht0);
        float ls1 = __low2float(ht1) + __high2float(ht1);

        const bool changed = (mn0 != old0) || (mn1 != old1);
        if (__any_sync(0xffffffffu, changed)) {
            const float c0 = ex2f(old0 - mn0);
            const float c1 = ex2f(old1 - mn1);
            sAcc0 = sAcc0 * c0 + ls0;
            sAcc1 = sAcc1 * c1 + ls1;
#pragma unroll
            for (int nn = 0; nn < 8; nn++) {
                o[nn][0] *= c0; o[nn][1] *= c0;
                o[nn][2] *= c1; o[nn][3] *= c1;
            }
        } else {
            sAcc0 += ls0;
            sAcc1 += ls1;
        }

        // ---- O += P.V (fp16) ----
#pragma unroll
        for (int ks = 0; ks < 4; ks++) {
            unsigned pa[4];
            pa[0] = p0[2*ks];
            pa[1] = p1[2*ks];
            pa[2] = p0[2*ks+1];
            pa[3] = p1[2*ks+1];
#pragma unroll
            for (int np = 0; np < 4; np++) {
                const int vr = ks * 16 + vrow_b;
                unsigned off = (unsigned)(vr * 128)
                             + (((unsigned)(np * 32) + vcolb) ^ (((unsigned)(vr & 7)) << 4));
                unsigned vf[4];
                ldsm4t(vf[0], vf[1], vf[2], vf[3], stg + 8192 + off);
                mma_f16(o[2*np],   pa, vf[0], vf[1]);
                mma_f16(o[2*np+1], pa, vf[2], vf[3]);
            }
        }
    }

    // ---- final cross-lane sum reduction ----
    float sL0 = sAcc0, sL1 = sAcc1;
    sL0 += __shfl_xor_sync(0xffffffffu, sL0, 1);
    sL0 += __shfl_xor_sync(0xffffffffu, sL0, 2);
    sL1 += __shfl_xor_sync(0xffffffffu, sL1, 1);
    sL1 += __shfl_xor_sync(0xffffffffu, sL1, 2);

    // ---- normalize + emit fp16 into g_AOh ----
    const float inv0 = 1.f / sL0, inv1 = 1.f / sL1;
    const int qr = q0 + wid * 16 + (lane >> 2);
    const size_t base0 = ((size_t)(b * SEQ + qr)) * DIM + h * HD;
    const size_t base1 = base0 + (size_t)8 * DIM;
#pragma unroll
    for (int nn = 0; nn < 8; nn++) {
        const int c = nn * 8 + (lane & 3) * 2;
        *(unsigned*)(g_AOh + base0 + c) = packh2(o[nn][0] * inv0, o[nn][1] * inv0);
        *(unsigned*)(g_AOh + base1 + c) = packh2(o[nn][2] * inv1, o[nn][3] * inv1);
    }
}

// ---------------------------------------------------------------------------
extern "C" void kernel_launch(void* const* d_in, const int* in_sizes, int n_in,
                              void* d_out, int out_size)
{
    const float* x     = (const float*)d_in[0];
    const float* mask  = (const float*)d_in[1];
    const float* bias  = (const float*)d_in[2];
    const float* Wqkv  = (const float*)d_in[3];
    const float* bqkv  = (const float*)d_in[4];
    const float* Wout  = (const float*)d_in[5];
    const float* bout  = (const float*)d_in[6];
    float* out = (float*)d_out;

    cudaFuncSetAttribute(mma_gemm_kernel,
                         cudaFuncAttributeMaxDynamicSharedMemorySize, GEMM_SMEM);
    cudaFuncSetAttribute(attn_mma_kernel,
                         cudaFuncAttributeMaxDynamicSharedMemorySize, ATTN_SMEM);

    __half *x16, *w1h, *w2h, *aoh;
    cudaGetSymbolAddress((void**)&x16, g_X16);
    cudaGetSymbolAddress((void**)&w1h, g_W1h);
    cudaGetSymbolAddress((void**)&w2h, g_W2h);
    cudaGetSymbolAddress((void**)&aoh, g_AOh);

    conv_x16_kernel<<<(MROWS * DIM / 4 + 255) / 256, 256>>>(x, x16,
                                                            MROWS * DIM / 4);
    conv_transpose_kernel<<<dim3(DIM / 32, QKVN / 32), dim3(32, 8)>>>(
        Wqkv, w1h, DIM, QKVN);
    conv_transpose_kernel<<<dim3(DIM / 32, DIM / 32), dim3(32, 8)>>>(
        Wout, w2h, DIM, DIM);
    mb_kernel<<<(BATCH * SEQ * SEQ / 8 + 255) / 256, 256>>>(
        mask, bias, BATCH * SEQ * SEQ / 8);

    mma_gemm_kernel<<<dim3(QKVN / 128, MROWS / 128), 256, GEMM_SMEM>>>(
        x16, w1h, bqkv, nullptr, 1);

    attn_mma_kernel<<<dim3(SEQ / 128, BATCH * NH), 256, ATTN_SMEM>>>();

    mma_gemm_kernel<<<dim3(DIM / 128, MROWS / 128), 256, GEMM_SMEM>>>(
        aoh, w2h, bout, out, 0);
}